// round 1
// baseline (speedup 1.0000x reference)
#include <cuda_runtime.h>
#include <math.h>

#define BSZ 4
#define NA 64
#define TT 128
#define DD 128
#define HH 8
#define DH 16
#define LL 3
#define DFF 512
#define EE 65536
#define NNODE (TT*NA)          /* 8192 */
#define ROWS (BSZ*NA*TT)       /* 32768 */
#define EPSV 1e-5f

/* ------------------ scratch (static device globals, no allocs) -------- */
__device__ float g_x[ROWS*DD];
__device__ float g_oute[ROWS*DD];
__device__ float g_q[ROWS*DD];
__device__ float g_k[ROWS*DD];
__device__ float g_v[ROWS*DD];
__device__ float g_ao[ROWS*DD];
__device__ float g_h1[ROWS*DD];
__device__ float g_ff1[ROWS*DFF];
__device__ float g_tmp[ROWS*DD];
__device__ float g_s[BSZ*NNODE];
__device__ float g_gr[BSZ*NNODE];
__device__ float g_stats[2];

/* ------------------ embed: x = ahf @ hist_w + hist_b ; out_e = x + PE -- */
__global__ void embed_kernel(const float* __restrict__ ahf,
                             const float* __restrict__ hw,
                             const float* __restrict__ hb) {
    int i = blockIdx.x * 256 + threadIdx.x;
    if (i >= ROWS*DD) return;
    int r = i >> 7;
    int d = i & 127;
    int t = r & (TT-1);
    float a0 = ahf[r*3+0], a1 = ahf[r*3+1], a2 = ahf[r*3+2];
    float xv = a0*hw[d] + a1*hw[DD+d] + a2*hw[2*DD+d] + hb[d];
    g_x[i] = xv;
    int ii = (d >> 1) * 2;
    float freq = __expf(-logf(10000.0f) * (float)ii / (float)DD);
    float ang = (float)t * freq;
    float pe = (d & 1) ? cosf(ang) : sinf(ang);
    g_oute[i] = xv + pe;
}

/* ------------------ tiled SGEMM: C = A(MxK) @ W(KxN) + bias, opt relu -- */
template<int RELU>
__global__ void gemm_kernel(const float* __restrict__ A,
                            const float* __restrict__ W,
                            const float* __restrict__ bias,
                            float* __restrict__ C,
                            int M, int N, int K) {
    __shared__ float As[16][65];   /* [k][m], padded: conflict-free stores */
    __shared__ float Ws[16][64];   /* [k][n] */
    int tid = threadIdx.x;         /* 256 threads */
    int tx = tid & 15, ty = tid >> 4;
    int bm = blockIdx.y * 64, bn = blockIdx.x * 64;
    int lar = tid >> 4, lac = tid & 15;   /* A loader */
    int lwr = tid >> 6, lwc = tid & 63;   /* W loader */
    float acc[4][4];
    #pragma unroll
    for (int i = 0; i < 4; i++)
        #pragma unroll
        for (int j = 0; j < 4; j++) acc[i][j] = 0.f;

    for (int k0 = 0; k0 < K; k0 += 16) {
        #pragma unroll
        for (int p = 0; p < 4; p++) {
            int m = lar + p*16;
            As[lac][m] = A[(size_t)(bm + m)*K + k0 + lac];
        }
        #pragma unroll
        for (int p = 0; p < 4; p++) {
            int kk = lwr + p*4;
            Ws[kk][lwc] = W[(size_t)(k0 + kk)*N + bn + lwc];
        }
        __syncthreads();
        #pragma unroll
        for (int k = 0; k < 16; k++) {
            float a[4], b[4];
            #pragma unroll
            for (int i = 0; i < 4; i++) a[i] = As[k][ty*4+i];
            #pragma unroll
            for (int j = 0; j < 4; j++) b[j] = Ws[k][tx*4+j];
            #pragma unroll
            for (int i = 0; i < 4; i++)
                #pragma unroll
                for (int j = 0; j < 4; j++)
                    acc[i][j] += a[i]*b[j];
        }
        __syncthreads();
    }
    #pragma unroll
    for (int i = 0; i < 4; i++) {
        int m = bm + ty*4 + i;
        #pragma unroll
        for (int j = 0; j < 4; j++) {
            int n = bn + tx*4 + j;
            float v = acc[i][j] + bias[n];
            if (RELU) v = fmaxf(v, 0.f);
            C[(size_t)m*N + n] = v;
        }
    }
}

/* ------------------ attention: one block per (b,n,h), 128 threads ------ */
__global__ void attn_kernel(const float* __restrict__ Q,
                            const float* __restrict__ K,
                            const float* __restrict__ V,
                            float* __restrict__ O) {
    __shared__ float ks[TT][DH];
    __shared__ float vs[TT][DH];
    int bh = blockIdx.x;
    int h  = bh & (HH-1);
    int bn = bh >> 3;
    size_t base = (size_t)bn*TT*DD + h*DH;
    int tid = threadIdx.x;  /* 128: one query row each */

    const float4* kp = (const float4*)(K + base + (size_t)tid*DD);
    const float4* vp = (const float4*)(V + base + (size_t)tid*DD);
    float4* ksp = (float4*)&ks[tid][0];
    float4* vsp = (float4*)&vs[tid][0];
    #pragma unroll
    for (int j = 0; j < 4; j++) { ksp[j] = kp[j]; vsp[j] = vp[j]; }

    float qr[DH];
    const float4* qp = (const float4*)(Q + base + (size_t)tid*DD);
    #pragma unroll
    for (int j = 0; j < 4; j++) ((float4*)qr)[j] = qp[j];
    __syncthreads();

    float mx = -1e30f, lsum = 0.f;
    float acc[DH];
    #pragma unroll
    for (int d2 = 0; d2 < DH; d2++) acc[d2] = 0.f;

    for (int j = 0; j < TT; j++) {
        float s = 0.f;
        #pragma unroll
        for (int d2 = 0; d2 < DH; d2++) s += qr[d2]*ks[j][d2];
        s *= 0.25f;  /* 1/sqrt(16) */
        float mn = fmaxf(mx, s);
        float corr = __expf(mx - mn);
        float p = __expf(s - mn);
        lsum = lsum*corr + p;
        #pragma unroll
        for (int d2 = 0; d2 < DH; d2++) acc[d2] = acc[d2]*corr + p*vs[j][d2];
        mx = mn;
    }
    float inv = 1.f/lsum;
    float* op = O + base + (size_t)tid*DD;
    #pragma unroll
    for (int d2 = 0; d2 < DH; d2++) op[d2] = acc[d2]*inv;
}

/* ------------------ out = LayerNorm(A + Bv) * g + beta ------------------ */
__global__ void add_ln_kernel(const float* __restrict__ A,
                              const float* __restrict__ Bv,
                              const float* __restrict__ g,
                              const float* __restrict__ bet,
                              float* __restrict__ out) {
    int r = blockIdx.x;
    int tid = threadIdx.x;  /* 128 */
    float x = A[(size_t)r*DD + tid] + Bv[(size_t)r*DD + tid];
    float s = x, sq = x*x;
    #pragma unroll
    for (int o = 16; o > 0; o >>= 1) {
        s  += __shfl_xor_sync(0xffffffffu, s, o);
        sq += __shfl_xor_sync(0xffffffffu, sq, o);
    }
    __shared__ float ss[4], ssq[4];
    int w = tid >> 5, ln = tid & 31;
    if (ln == 0) { ss[w] = s; ssq[w] = sq; }
    __syncthreads();
    s  = ss[0]+ss[1]+ss[2]+ss[3];
    sq = ssq[0]+ssq[1]+ssq[2]+ssq[3];
    float m = s * (1.f/DD);
    float var = sq * (1.f/DD) - m*m;
    out[(size_t)r*DD + tid] = (x - m)*rsqrtf(var + EPSV)*g[tid] + bet[tid];
}

/* ------------------ s[b, t*NA+n] = dot(out_e row, x row) --------------- */
__global__ void dot_kernel() {
    int r  = blockIdx.x*8 + (threadIdx.x >> 5);
    int ln = threadIdx.x & 31;
    const float* a = g_oute + (size_t)r*DD;
    const float* c = g_x    + (size_t)r*DD;
    float s = 0.f;
    #pragma unroll
    for (int j = ln; j < DD; j += 32) s += a[j]*c[j];
    #pragma unroll
    for (int o = 16; o > 0; o >>= 1) s += __shfl_xor_sync(0xffffffffu, s, o);
    if (ln == 0) {
        int b = r / (NA*TT);
        int rem = r % (NA*TT);
        int n = rem >> 7;      /* rem / T */
        int t = rem & 127;
        g_s[b*NNODE + t*NA + n] = s;
    }
}

__global__ void zero_kernel() {
    int i = blockIdx.x*256 + threadIdx.x;
    if (i < BSZ*NNODE) g_gr[i] = 0.f;
}

/* ------------------ edge segment-sum via atomics ----------------------- */
__global__ void agg_kernel(const int* __restrict__ ei,
                           const float* __restrict__ ew) {
    int i = blockIdx.x*256 + threadIdx.x;
    if (i >= BSZ*EE) return;
    int b = i >> 16;          /* i / E */
    int e = i & (EE-1);
    int src = ei[(size_t)b*2*EE + e];
    int dst = ei[(size_t)b*2*EE + EE + e];
    atomicAdd(&g_gr[b*NNODE + dst], ew[(size_t)b*EE + e] * g_s[b*NNODE + src]);
}

/* ------------------ global mean / rsqrt(var) --------------------------- */
__global__ void stats_kernel() {
    int tid = threadIdx.x;  /* 1024 */
    float s = 0.f, sq = 0.f;
    for (int i = tid; i < BSZ*NNODE; i += 1024) {
        float v = g_gr[i];
        s += v; sq += v*v;
    }
    #pragma unroll
    for (int o = 16; o > 0; o >>= 1) {
        s  += __shfl_xor_sync(0xffffffffu, s, o);
        sq += __shfl_xor_sync(0xffffffffu, sq, o);
    }
    __shared__ float ss[32], ssq[32];
    int w = tid >> 5, ln = tid & 31;
    if (ln == 0) { ss[w] = s; ssq[w] = sq; }
    __syncthreads();
    if (tid == 0) {
        float ts = 0.f, tq = 0.f;
        #pragma unroll
        for (int j = 0; j < 32; j++) { ts += ss[j]; tq += ssq[j]; }
        float m = ts / (float)(BSZ*NNODE);
        float var = tq / (float)(BSZ*NNODE) - m*m;
        g_stats[0] = m;
        g_stats[1] = rsqrtf(var + EPSV);
    }
}

/* ------------------ final: out[b,n,t,d] = bn(g)[b,t,n]*lw[d]+lb[d] ----- */
__global__ void final_kernel(const float* __restrict__ bng,
                             const float* __restrict__ bnb,
                             const float* __restrict__ lw,
                             const float* __restrict__ lb,
                             float* __restrict__ out) {
    int i = blockIdx.x*256 + threadIdx.x;
    if (i >= ROWS*DD) return;
    int d = i & 127;
    int r = i >> 7;              /* (b*NA + n)*T + t */
    int t = r & 127;
    int bn = r >> 7;
    int n = bn & 63;
    int b = bn >> 6;
    float gv = (g_gr[b*NNODE + t*NA + n] - g_stats[0]) * g_stats[1] * bng[0] + bnb[0];
    out[i] = gv * lw[d] + lb[d];
}

/* ---------------------------------------------------------------------- */
extern "C" void kernel_launch(void* const* d_in, const int* in_sizes, int n_in,
                              void* d_out, int out_size) {
    const float* ahf  = (const float*)d_in[0];
    const int*   ei   = (const int*)  d_in[1];
    const float* ew   = (const float*)d_in[2];
    const float* hw   = (const float*)d_in[3];
    const float* hb   = (const float*)d_in[4];
    const float* wq   = (const float*)d_in[5];
    const float* bq   = (const float*)d_in[6];
    const float* wk   = (const float*)d_in[7];
    const float* bk   = (const float*)d_in[8];
    const float* wv   = (const float*)d_in[9];
    const float* bv   = (const float*)d_in[10];
    const float* wo   = (const float*)d_in[11];
    const float* bo   = (const float*)d_in[12];
    const float* ln1g = (const float*)d_in[13];
    const float* ln1b = (const float*)d_in[14];
    const float* fw1  = (const float*)d_in[15];
    const float* fb1  = (const float*)d_in[16];
    const float* fw2  = (const float*)d_in[17];
    const float* fb2  = (const float*)d_in[18];
    const float* ln2g = (const float*)d_in[19];
    const float* ln2b = (const float*)d_in[20];
    const float* bng  = (const float*)d_in[21];
    const float* bnb  = (const float*)d_in[22];
    const float* lgw  = (const float*)d_in[23];
    const float* lgb  = (const float*)d_in[24];
    float* out = (float*)d_out;

    float *px, *poute, *pq, *pk, *pv, *pao, *ph1, *pff1, *ptmp;
    cudaGetSymbolAddress((void**)&px,    g_x);
    cudaGetSymbolAddress((void**)&poute, g_oute);
    cudaGetSymbolAddress((void**)&pq,    g_q);
    cudaGetSymbolAddress((void**)&pk,    g_k);
    cudaGetSymbolAddress((void**)&pv,    g_v);
    cudaGetSymbolAddress((void**)&pao,   g_ao);
    cudaGetSymbolAddress((void**)&ph1,   g_h1);
    cudaGetSymbolAddress((void**)&pff1,  g_ff1);
    cudaGetSymbolAddress((void**)&ptmp,  g_tmp);

    embed_kernel<<<(ROWS*DD)/256, 256>>>(ahf, hw, hb);

    dim3 gp(DD/64, ROWS/64);     /* (2, 512)  proj / ff2 */
    dim3 g1(DFF/64, ROWS/64);    /* (8, 512)  ff1 */

    for (int l = 0; l < LL; l++) {
        const float* Wq = wq + (size_t)l*DD*DD;
        const float* Wk = wk + (size_t)l*DD*DD;
        const float* Wv = wv + (size_t)l*DD*DD;
        const float* Wo = wo + (size_t)l*DD*DD;
        gemm_kernel<0><<<gp, 256>>>(poute, Wq, bq + l*DD, pq, ROWS, DD, DD);
        gemm_kernel<0><<<gp, 256>>>(poute, Wk, bk + l*DD, pk, ROWS, DD, DD);
        gemm_kernel<0><<<gp, 256>>>(poute, Wv, bv + l*DD, pv, ROWS, DD, DD);
        attn_kernel<<<BSZ*NA*HH, 128>>>(pq, pk, pv, pao);
        gemm_kernel<0><<<gp, 256>>>(pao, Wo, bo + l*DD, ptmp, ROWS, DD, DD);
        add_ln_kernel<<<ROWS, 128>>>(poute, ptmp, ln1g + l*DD, ln1b + l*DD, ph1);
        gemm_kernel<1><<<g1, 256>>>(ph1, fw1 + (size_t)l*DD*DFF, fb1 + l*DFF,
                                    pff1, ROWS, DFF, DD);
        gemm_kernel<0><<<gp, 256>>>(pff1, fw2 + (size_t)l*DFF*DD, fb2 + l*DD,
                                    ptmp, ROWS, DD, DFF);
        add_ln_kernel<<<ROWS, 128>>>(ph1, ptmp, ln2g + l*DD, ln2b + l*DD, poute);
    }

    dot_kernel<<<ROWS/8, 256>>>();
    zero_kernel<<<(BSZ*NNODE + 255)/256, 256>>>();
    agg_kernel<<<(BSZ*EE + 255)/256, 256>>>(ei, ew);
    stats_kernel<<<1, 1024>>>();
    final_kernel<<<(ROWS*DD)/256, 256>>>(bng, bnb, lgw, lgb, out);
}

// round 2
// speedup vs baseline: 1.7279x; 1.7279x over previous
#include <cuda_runtime.h>
#include <math.h>
#include <stdint.h>

#define BSZ 4
#define NA 64
#define TT 128
#define DD 128
#define HH 8
#define DH 16
#define LL 3
#define DFF 512
#define EE 65536
#define NNODE (TT*NA)          /* 8192 */
#define ROWS (BSZ*NA*TT)       /* 32768 */
#define EPSV 1e-5f
#define PADS 136               /* smem row stride (floats) */

/* ------------------ scratch (static device globals, no allocs) -------- */
__device__ float g_x[ROWS*DD];
__device__ float g_oute[ROWS*DD];
__device__ float g_q[ROWS*DD];
__device__ float g_k[ROWS*DD];
__device__ float g_v[ROWS*DD];
__device__ float g_ao[ROWS*DD];
__device__ float g_h1[ROWS*DD];
__device__ float g_ff1[ROWS*DFF];
__device__ float g_tmp[ROWS*DD];
__device__ float g_s[BSZ*NNODE];
__device__ float g_gr[BSZ*NNODE];
__device__ float g_stats[2];

/* ------------------ embed: x = ahf @ hist_w + hist_b ; out_e = x + PE -- */
__global__ void embed_kernel(const float* __restrict__ ahf,
                             const float* __restrict__ hw,
                             const float* __restrict__ hb) {
    int i = blockIdx.x * 256 + threadIdx.x;
    if (i >= ROWS*DD) return;
    int r = i >> 7;
    int d = i & 127;
    int t = r & (TT-1);
    float a0 = ahf[r*3+0], a1 = ahf[r*3+1], a2 = ahf[r*3+2];
    float xv = a0*hw[d] + a1*hw[DD+d] + a2*hw[2*DD+d] + hb[d];
    g_x[i] = xv;
    int ii = (d >> 1) * 2;
    float freq = __expf(-logf(10000.0f) * (float)ii / (float)DD);
    float ang = (float)t * freq;
    float pe = (d & 1) ? cosf(ang) : sinf(ang);
    g_oute[i] = xv + pe;
}

/* ------------------ tf32 helpers ---------------------------------------- */
__device__ __forceinline__ uint32_t f2tf(float f) {
    uint32_t u;
    asm("cvt.rna.tf32.f32 %0, %1;" : "=r"(u) : "f"(f));
    return u;
}

__device__ __forceinline__ void mma_tf32(float* c, const uint32_t* a,
                                         const uint32_t* b) {
    asm volatile(
        "mma.sync.aligned.m16n8k8.row.col.f32.tf32.tf32.f32 "
        "{%0,%1,%2,%3}, {%4,%5,%6,%7}, {%8,%9}, {%0,%1,%2,%3};\n"
        : "+f"(c[0]), "+f"(c[1]), "+f"(c[2]), "+f"(c[3])
        : "r"(a[0]), "r"(a[1]), "r"(a[2]), "r"(a[3]),
          "r"(b[0]), "r"(b[1]));
}

/* ------------------ tf32 tensor-core GEMM: C = A(MxK)@W(KxN)+bias ------- */
/* 128x128 CTA tile, 256 thr = 8 warps (2x4), 64x32 warp tile, BK=32.      */
template<int RELU>
__device__ __forceinline__ void gemm_body(const float* __restrict__ A,
                                          const float* __restrict__ W,
                                          const float* __restrict__ bias,
                                          float* __restrict__ C,
                                          int M, int N, int K) {
    __shared__ uint32_t As[32*PADS];   /* [k][m] transposed */
    __shared__ uint32_t Bs[32*PADS];   /* [k][n] */
    int tid  = threadIdx.x;
    int lane = tid & 31;
    int wid  = tid >> 5;
    int wm   = wid >> 2;    /* 0..1 -> 64-row slab */
    int wn   = wid & 3;     /* 0..3 -> 32-col slab */
    int grp  = lane >> 2;   /* 0..7 */
    int qid  = lane & 3;    /* 0..3 */
    int bm = blockIdx.y * 128, bn = blockIdx.x * 128;

    float acc[4][4][4];
    #pragma unroll
    for (int mt = 0; mt < 4; mt++)
        #pragma unroll
        for (int nt = 0; nt < 4; nt++)
            #pragma unroll
            for (int i = 0; i < 4; i++) acc[mt][nt][i] = 0.f;

    /* loader mapping */
    int am  = tid & 127;           /* A row within tile */
    int akb = (tid >> 7) * 16;     /* A k base (0 or 16) */
    int bn4 = (tid & 31) * 4;      /* B col within tile */
    int bkr = tid >> 5;            /* B k row (0..7), +8j */

    const float* Ag = A + (size_t)(bm + am)*K + akb;
    const float* Bg = W + (size_t)bkr*N + bn + bn4;

    float4 apf[4], bpf[4];
    #pragma unroll
    for (int j = 0; j < 4; j++) apf[j] = *(const float4*)(Ag + 4*j);
    #pragma unroll
    for (int j = 0; j < 4; j++) bpf[j] = *(const float4*)(Bg + (size_t)(8*j)*N);

    /* store tile 0 */
    #pragma unroll
    for (int j = 0; j < 4; j++) {
        int kk = akb + 4*j;
        As[(kk+0)*PADS + am] = f2tf(apf[j].x);
        As[(kk+1)*PADS + am] = f2tf(apf[j].y);
        As[(kk+2)*PADS + am] = f2tf(apf[j].z);
        As[(kk+3)*PADS + am] = f2tf(apf[j].w);
    }
    #pragma unroll
    for (int j = 0; j < 4; j++) {
        uint4 u;
        u.x = f2tf(bpf[j].x); u.y = f2tf(bpf[j].y);
        u.z = f2tf(bpf[j].z); u.w = f2tf(bpf[j].w);
        *(uint4*)&Bs[(bkr + 8*j)*PADS + bn4] = u;
    }
    __syncthreads();

    int ntile = K >> 5;
    for (int t = 0; t < ntile; t++) {
        if (t + 1 < ntile) {
            const float* Ag2 = Ag + (t+1)*32;
            const float* Bg2 = Bg + (size_t)(t+1)*32*N;
            #pragma unroll
            for (int j = 0; j < 4; j++) apf[j] = *(const float4*)(Ag2 + 4*j);
            #pragma unroll
            for (int j = 0; j < 4; j++) bpf[j] = *(const float4*)(Bg2 + (size_t)(8*j)*N);
        }
        #pragma unroll
        for (int ks = 0; ks < 4; ks++) {
            int kk = ks * 8;
            uint32_t af[4][4], bf[4][2];
            #pragma unroll
            for (int mt = 0; mt < 4; mt++) {
                int m0 = wm*64 + mt*16;
                af[mt][0] = As[(kk+qid  )*PADS + m0 + grp    ];
                af[mt][1] = As[(kk+qid  )*PADS + m0 + grp + 8];
                af[mt][2] = As[(kk+qid+4)*PADS + m0 + grp    ];
                af[mt][3] = As[(kk+qid+4)*PADS + m0 + grp + 8];
            }
            #pragma unroll
            for (int nt = 0; nt < 4; nt++) {
                int n0 = wn*32 + nt*8;
                bf[nt][0] = Bs[(kk+qid  )*PADS + n0 + grp];
                bf[nt][1] = Bs[(kk+qid+4)*PADS + n0 + grp];
            }
            #pragma unroll
            for (int mt = 0; mt < 4; mt++)
                #pragma unroll
                for (int nt = 0; nt < 4; nt++)
                    mma_tf32(acc[mt][nt], af[mt], bf[nt]);
        }
        __syncthreads();
        if (t + 1 < ntile) {
            #pragma unroll
            for (int j = 0; j < 4; j++) {
                int kk = akb + 4*j;
                As[(kk+0)*PADS + am] = f2tf(apf[j].x);
                As[(kk+1)*PADS + am] = f2tf(apf[j].y);
                As[(kk+2)*PADS + am] = f2tf(apf[j].z);
                As[(kk+3)*PADS + am] = f2tf(apf[j].w);
            }
            #pragma unroll
            for (int j = 0; j < 4; j++) {
                uint4 u;
                u.x = f2tf(bpf[j].x); u.y = f2tf(bpf[j].y);
                u.z = f2tf(bpf[j].z); u.w = f2tf(bpf[j].w);
                *(uint4*)&Bs[(bkr + 8*j)*PADS + bn4] = u;
            }
            __syncthreads();
        }
    }

    /* epilogue */
    #pragma unroll
    for (int mt = 0; mt < 4; mt++) {
        int r0 = bm + wm*64 + mt*16 + grp;
        #pragma unroll
        for (int nt = 0; nt < 4; nt++) {
            int c0 = bn + wn*32 + nt*8 + qid*2;
            float b0 = bias[c0], b1 = bias[c0+1];
            float v0 = acc[mt][nt][0] + b0;
            float v1 = acc[mt][nt][1] + b1;
            float v2 = acc[mt][nt][2] + b0;
            float v3 = acc[mt][nt][3] + b1;
            if (RELU) {
                v0 = fmaxf(v0, 0.f); v1 = fmaxf(v1, 0.f);
                v2 = fmaxf(v2, 0.f); v3 = fmaxf(v3, 0.f);
            }
            *(float2*)&C[(size_t)r0*N + c0]     = make_float2(v0, v1);
            *(float2*)&C[(size_t)(r0+8)*N + c0] = make_float2(v2, v3);
        }
    }
}

__global__ __launch_bounds__(256)
void gemm_tc(const float* __restrict__ A, const float* __restrict__ W,
             const float* __restrict__ bias, float* __restrict__ C,
             int M, int N, int K) {
    gemm_body<0>(A, W, bias, C, M, N, K);
}

__global__ __launch_bounds__(256)
void gemm_tc_relu(const float* __restrict__ A, const float* __restrict__ W,
                  const float* __restrict__ bias, float* __restrict__ C,
                  int M, int N, int K) {
    gemm_body<1>(A, W, bias, C, M, N, K);
}

/* fused q/k/v: blockIdx.z selects weight/bias/output */
__global__ __launch_bounds__(256)
void gemm_tc_qkv(const float* __restrict__ A,
                 const float* __restrict__ Wq, const float* __restrict__ Wk,
                 const float* __restrict__ Wv,
                 const float* __restrict__ bq, const float* __restrict__ bk,
                 const float* __restrict__ bv,
                 float* __restrict__ Cq, float* __restrict__ Ck,
                 float* __restrict__ Cv) {
    const float* W; const float* bi; float* C;
    if (blockIdx.z == 0)      { W = Wq; bi = bq; C = Cq; }
    else if (blockIdx.z == 1) { W = Wk; bi = bk; C = Ck; }
    else                      { W = Wv; bi = bv; C = Cv; }
    gemm_body<0>(A, W, bi, C, ROWS, DD, DD);
}

/* ------------------ attention: one block per (b,n,h), 128 threads ------ */
__global__ void attn_kernel(const float* __restrict__ Q,
                            const float* __restrict__ K,
                            const float* __restrict__ V,
                            float* __restrict__ O) {
    __shared__ float ks[TT][DH];
    __shared__ float vs[TT][DH];
    int bh = blockIdx.x;
    int h  = bh & (HH-1);
    int bn = bh >> 3;
    size_t base = (size_t)bn*TT*DD + h*DH;
    int tid = threadIdx.x;  /* 128: one query row each */

    const float4* kp = (const float4*)(K + base + (size_t)tid*DD);
    const float4* vp = (const float4*)(V + base + (size_t)tid*DD);
    float4* ksp = (float4*)&ks[tid][0];
    float4* vsp = (float4*)&vs[tid][0];
    #pragma unroll
    for (int j = 0; j < 4; j++) { ksp[j] = kp[j]; vsp[j] = vp[j]; }

    float qr[DH];
    const float4* qp = (const float4*)(Q + base + (size_t)tid*DD);
    #pragma unroll
    for (int j = 0; j < 4; j++) ((float4*)qr)[j] = qp[j];
    __syncthreads();

    float mx = -1e30f, lsum = 0.f;
    float acc[DH];
    #pragma unroll
    for (int d2 = 0; d2 < DH; d2++) acc[d2] = 0.f;

    for (int j = 0; j < TT; j++) {
        float s = 0.f;
        #pragma unroll
        for (int d2 = 0; d2 < DH; d2++) s += qr[d2]*ks[j][d2];
        s *= 0.25f;  /* 1/sqrt(16) */
        float mn = fmaxf(mx, s);
        float corr = __expf(mx - mn);
        float p = __expf(s - mn);
        lsum = lsum*corr + p;
        #pragma unroll
        for (int d2 = 0; d2 < DH; d2++) acc[d2] = acc[d2]*corr + p*vs[j][d2];
        mx = mn;
    }
    float inv = 1.f/lsum;
    float* op = O + base + (size_t)tid*DD;
    #pragma unroll
    for (int d2 = 0; d2 < DH; d2++) op[d2] = acc[d2]*inv;
}

/* ------------------ out = LayerNorm(A + Bv) * g + beta ------------------ */
__global__ void add_ln_kernel(const float* __restrict__ A,
                              const float* __restrict__ Bv,
                              const float* __restrict__ g,
                              const float* __restrict__ bet,
                              float* __restrict__ out) {
    int r = blockIdx.x;
    int tid = threadIdx.x;  /* 128 */
    float x = A[(size_t)r*DD + tid] + Bv[(size_t)r*DD + tid];
    float s = x, sq = x*x;
    #pragma unroll
    for (int o = 16; o > 0; o >>= 1) {
        s  += __shfl_xor_sync(0xffffffffu, s, o);
        sq += __shfl_xor_sync(0xffffffffu, sq, o);
    }
    __shared__ float ss[4], ssq[4];
    int w = tid >> 5, ln = tid & 31;
    if (ln == 0) { ss[w] = s; ssq[w] = sq; }
    __syncthreads();
    s  = ss[0]+ss[1]+ss[2]+ss[3];
    sq = ssq[0]+ssq[1]+ssq[2]+ssq[3];
    float m = s * (1.f/DD);
    float var = sq * (1.f/DD) - m*m;
    out[(size_t)r*DD + tid] = (x - m)*rsqrtf(var + EPSV)*g[tid] + bet[tid];
}

/* ------------------ s[b, t*NA+n] = dot(out_e row, x row) --------------- */
__global__ void dot_kernel() {
    int r  = blockIdx.x*8 + (threadIdx.x >> 5);
    int ln = threadIdx.x & 31;
    const float* a = g_oute + (size_t)r*DD;
    const float* c = g_x    + (size_t)r*DD;
    float s = 0.f;
    #pragma unroll
    for (int j = ln; j < DD; j += 32) s += a[j]*c[j];
    #pragma unroll
    for (int o = 16; o > 0; o >>= 1) s += __shfl_xor_sync(0xffffffffu, s, o);
    if (ln == 0) {
        int b = r / (NA*TT);
        int rem = r % (NA*TT);
        int n = rem >> 7;
        int t = rem & 127;
        g_s[b*NNODE + t*NA + n] = s;
    }
}

__global__ void zero_kernel() {
    int i = blockIdx.x*256 + threadIdx.x;
    if (i < BSZ*NNODE) g_gr[i] = 0.f;
}

/* ------------------ edge segment-sum via atomics ----------------------- */
__global__ void agg_kernel(const int* __restrict__ ei,
                           const float* __restrict__ ew) {
    int i = blockIdx.x*256 + threadIdx.x;
    if (i >= BSZ*EE) return;
    int b = i >> 16;
    int e = i & (EE-1);
    int src = ei[(size_t)b*2*EE + e];
    int dst = ei[(size_t)b*2*EE + EE + e];
    atomicAdd(&g_gr[b*NNODE + dst], ew[(size_t)b*EE + e] * g_s[b*NNODE + src]);
}

/* ------------------ global mean / rsqrt(var) --------------------------- */
__global__ void stats_kernel() {
    int tid = threadIdx.x;  /* 1024 */
    float s = 0.f, sq = 0.f;
    for (int i = tid; i < BSZ*NNODE; i += 1024) {
        float v = g_gr[i];
        s += v; sq += v*v;
    }
    #pragma unroll
    for (int o = 16; o > 0; o >>= 1) {
        s  += __shfl_xor_sync(0xffffffffu, s, o);
        sq += __shfl_xor_sync(0xffffffffu, sq, o);
    }
    __shared__ float ss[32], ssq[32];
    int w = tid >> 5, ln = tid & 31;
    if (ln == 0) { ss[w] = s; ssq[w] = sq; }
    __syncthreads();
    if (tid == 0) {
        float ts = 0.f, tq = 0.f;
        #pragma unroll
        for (int j = 0; j < 32; j++) { ts += ss[j]; tq += ssq[j]; }
        float m = ts / (float)(BSZ*NNODE);
        float var = tq / (float)(BSZ*NNODE) - m*m;
        g_stats[0] = m;
        g_stats[1] = rsqrtf(var + EPSV);
    }
}

/* ------------------ final: out[b,n,t,d] = bn(g)[b,t,n]*lw[d]+lb[d] ----- */
__global__ void final_kernel(const float* __restrict__ bng,
                             const float* __restrict__ bnb,
                             const float* __restrict__ lw,
                             const float* __restrict__ lb,
                             float* __restrict__ out) {
    int i = blockIdx.x*256 + threadIdx.x;
    if (i >= ROWS*DD) return;
    int d = i & 127;
    int r = i >> 7;
    int t = r & 127;
    int bn = r >> 7;
    int n = bn & 63;
    int b = bn >> 6;
    float gv = (g_gr[b*NNODE + t*NA + n] - g_stats[0]) * g_stats[1] * bng[0] + bnb[0];
    out[i] = gv * lw[d] + lb[d];
}

/* ---------------------------------------------------------------------- */
extern "C" void kernel_launch(void* const* d_in, const int* in_sizes, int n_in,
                              void* d_out, int out_size) {
    const float* ahf  = (const float*)d_in[0];
    const int*   ei   = (const int*)  d_in[1];
    const float* ew   = (const float*)d_in[2];
    const float* hw   = (const float*)d_in[3];
    const float* hb   = (const float*)d_in[4];
    const float* wq   = (const float*)d_in[5];
    const float* bq   = (const float*)d_in[6];
    const float* wk   = (const float*)d_in[7];
    const float* bk   = (const float*)d_in[8];
    const float* wv   = (const float*)d_in[9];
    const float* bv   = (const float*)d_in[10];
    const float* wo   = (const float*)d_in[11];
    const float* bo   = (const float*)d_in[12];
    const float* ln1g = (const float*)d_in[13];
    const float* ln1b = (const float*)d_in[14];
    const float* fw1  = (const float*)d_in[15];
    const float* fb1  = (const float*)d_in[16];
    const float* fw2  = (const float*)d_in[17];
    const float* fb2  = (const float*)d_in[18];
    const float* ln2g = (const float*)d_in[19];
    const float* ln2b = (const float*)d_in[20];
    const float* bng  = (const float*)d_in[21];
    const float* bnb  = (const float*)d_in[22];
    const float* lgw  = (const float*)d_in[23];
    const float* lgb  = (const float*)d_in[24];
    float* out = (float*)d_out;

    float *px, *poute, *pq, *pk, *pv, *pao, *ph1, *pff1, *ptmp;
    cudaGetSymbolAddress((void**)&px,    g_x);
    cudaGetSymbolAddress((void**)&poute, g_oute);
    cudaGetSymbolAddress((void**)&pq,    g_q);
    cudaGetSymbolAddress((void**)&pk,    g_k);
    cudaGetSymbolAddress((void**)&pv,    g_v);
    cudaGetSymbolAddress((void**)&pao,   g_ao);
    cudaGetSymbolAddress((void**)&ph1,   g_h1);
    cudaGetSymbolAddress((void**)&pff1,  g_ff1);
    cudaGetSymbolAddress((void**)&ptmp,  g_tmp);

    embed_kernel<<<(ROWS*DD)/256, 256>>>(ahf, hw, hb);

    dim3 gqkv(DD/128, ROWS/128, 3);   /* (1, 256, 3) */
    dim3 gp(DD/128, ROWS/128);        /* (1, 256) */
    dim3 g1(DFF/128, ROWS/128);       /* (4, 256) */

    for (int l = 0; l < LL; l++) {
        const float* Wq = wq + (size_t)l*DD*DD;
        const float* Wk = wk + (size_t)l*DD*DD;
        const float* Wv = wv + (size_t)l*DD*DD;
        const float* Wo = wo + (size_t)l*DD*DD;
        gemm_tc_qkv<<<gqkv, 256>>>(poute, Wq, Wk, Wv,
                                   bq + l*DD, bk + l*DD, bv + l*DD,
                                   pq, pk, pv);
        attn_kernel<<<BSZ*NA*HH, 128>>>(pq, pk, pv, pao);
        gemm_tc<<<gp, 256>>>(pao, Wo, bo + l*DD, ptmp, ROWS, DD, DD);
        add_ln_kernel<<<ROWS, 128>>>(poute, ptmp, ln1g + l*DD, ln1b + l*DD, ph1);
        gemm_tc_relu<<<g1, 256>>>(ph1, fw1 + (size_t)l*DD*DFF, fb1 + l*DFF,
                                  pff1, ROWS, DFF, DD);
        gemm_tc<<<gp, 256>>>(pff1, fw2 + (size_t)l*DFF*DD, fb2 + l*DD,
                             ptmp, ROWS, DD, DFF);
        add_ln_kernel<<<ROWS, 128>>>(ph1, ptmp, ln2g + l*DD, ln2b + l*DD, poute);
    }

    dot_kernel<<<ROWS/8, 256>>>();
    zero_kernel<<<(BSZ*NNODE + 255)/256, 256>>>();
    agg_kernel<<<(BSZ*EE + 255)/256, 256>>>(ei, ew);
    stats_kernel<<<1, 1024>>>();
    final_kernel<<<(ROWS*DD)/256, 256>>>(bng, bnb, lgw, lgb, out);
}

// round 7
// speedup vs baseline: 1.8431x; 1.0666x over previous
#include <cuda_runtime.h>
#include <math.h>
#include <stdint.h>

#define BSZ 4
#define NA 64
#define TT 128
#define DD 128
#define HH 8
#define DH 16
#define LL 3
#define DFF 512
#define EE 65536
#define NNODE (TT*NA)          /* 8192 */
#define ROWS (BSZ*NA*TT)       /* 32768 */
#define EPSV 1e-5f
#define PADS 136               /* smem row stride (32-bit words) */
#define TILEW (32*PADS)        /* one stage: 32 k-rows */
#define SMEM_BYTES (4*TILEW*4) /* As[2] + Bs[2] = 69632 B */

/* ------------------ scratch (static device globals, no allocs) -------- */
__device__ float g_x[ROWS*DD];
__device__ float g_oute[ROWS*DD];
__device__ float g_q[ROWS*DD];
__device__ float g_k[ROWS*DD];
__device__ float g_v[ROWS*DD];
__device__ float g_ao[ROWS*DD];
__device__ float g_h1[ROWS*DD];
__device__ float g_ff1[ROWS*DFF];
__device__ float g_tmp[ROWS*DD];
__device__ float g_s[BSZ*NNODE];
__device__ float g_gr[BSZ*NNODE];
__device__ float g_stats[2];

/* ------------------ embed: x = ahf @ hist_w + hist_b ; out_e = x + PE -- */
__global__ void embed_kernel(const float* __restrict__ ahf,
                             const float* __restrict__ hw,
                             const float* __restrict__ hb) {
    int i = blockIdx.x * 256 + threadIdx.x;
    if (i >= ROWS*DD) return;
    int r = i >> 7;
    int d = i & 127;
    int t = r & (TT-1);
    float a0 = ahf[r*3+0], a1 = ahf[r*3+1], a2 = ahf[r*3+2];
    float xv = a0*hw[d] + a1*hw[DD+d] + a2*hw[2*DD+d] + hb[d];
    g_x[i] = xv;
    int ii = (d >> 1) * 2;
    float freq = __expf(-logf(10000.0f) * (float)ii / (float)DD);
    float ang = (float)t * freq;
    float pe = (d & 1) ? cosf(ang) : sinf(ang);
    g_oute[i] = xv + pe;
}

/* ------------------ tf32 / async helpers -------------------------------- */
__device__ __forceinline__ uint32_t f2tf(float f) {
    uint32_t u;
    asm("cvt.rna.tf32.f32 %0, %1;" : "=r"(u) : "f"(f));
    return u;
}

__device__ __forceinline__ void cp16(void* smem_dst, const void* gmem_src) {
    uint32_t s = (uint32_t)__cvta_generic_to_shared(smem_dst);
    asm volatile("cp.async.cg.shared.global [%0], [%1], 16;\n"
                 :: "r"(s), "l"(gmem_src));
}
__device__ __forceinline__ void cp_commit() {
    asm volatile("cp.async.commit_group;\n");
}
__device__ __forceinline__ void cp_wait_all() {
    asm volatile("cp.async.wait_group 0;\n");
}

__device__ __forceinline__ void mma_tf32(float* c, const uint32_t* a,
                                         const uint32_t* b) {
    asm volatile(
        "mma.sync.aligned.m16n8k8.row.col.f32.tf32.tf32.f32 "
        "{%0,%1,%2,%3}, {%4,%5,%6,%7}, {%8,%9}, {%0,%1,%2,%3};\n"
        : "+f"(c[0]), "+f"(c[1]), "+f"(c[2]), "+f"(c[3])
        : "r"(a[0]), "r"(a[1]), "r"(a[2]), "r"(a[3]),
          "r"(b[0]), "r"(b[1]));
}

/* ------------------ tf32 tensor-core GEMM: C = A(MxK)@W(KxN)+bias -------
   128x128 CTA tile, 256 thr = 8 warps (2x4), 64x32 warp tile, BK=32.
   Double-buffered smem; A via register prefetch (+cvt), B via cp.async.   */
template<int RELU>
__device__ __forceinline__ void gemm_body(const float* __restrict__ A,
                                          const float* __restrict__ W,
                                          const float* __restrict__ bias,
                                          float* __restrict__ C,
                                          int M, int N, int K) {
    extern __shared__ uint32_t dynsm[];
    uint32_t* As = dynsm;              /* 2 stages, tf32 [k][m] */
    float*    Bs = (float*)(dynsm + 2*TILEW);  /* 2 stages, fp32 [k][n] */

    int tid  = threadIdx.x;
    int lane = tid & 31;
    int wid  = tid >> 5;
    int wm   = wid >> 2;    /* 0..1 -> 64-row slab */
    int wn   = wid & 3;     /* 0..3 -> 32-col slab */
    int grp  = lane >> 2;   /* 0..7 */
    int qid  = lane & 3;    /* 0..3 */
    int bm = blockIdx.y * 128, bn = blockIdx.x * 128;

    float acc[4][4][4];
    #pragma unroll
    for (int mt = 0; mt < 4; mt++)
        #pragma unroll
        for (int nt = 0; nt < 4; nt++)
            #pragma unroll
            for (int i = 0; i < 4; i++) acc[mt][nt][i] = 0.f;

    /* loader mapping */
    int am  = tid & 127;           /* A row within tile */
    int akb = (tid >> 7) * 16;     /* A k base (0 or 16) */
    int bn4 = (tid & 31) * 4;      /* B col within tile */
    int bkr = tid >> 5;            /* B k row (0..7), +8j */

    const float* Ag = A + (size_t)(bm + am)*K + akb;
    const float* Bg = W + (size_t)bkr*N + bn + bn4;

    /* ---- prologue: tile 0 ---- */
    float4 apf[4];
    #pragma unroll
    for (int j = 0; j < 4; j++) apf[j] = *(const float4*)(Ag + 4*j);
    #pragma unroll
    for (int j = 0; j < 4; j++)
        cp16(&Bs[(bkr + 8*j)*PADS + bn4], Bg + (size_t)(8*j)*N);
    cp_commit();
    #pragma unroll
    for (int j = 0; j < 4; j++) {
        int kk = akb + 4*j;
        As[(kk+0)*PADS + am] = f2tf(apf[j].x);
        As[(kk+1)*PADS + am] = f2tf(apf[j].y);
        As[(kk+2)*PADS + am] = f2tf(apf[j].z);
        As[(kk+3)*PADS + am] = f2tf(apf[j].w);
    }

    int ntile = K >> 5;
    for (int t = 0; t < ntile; t++) {
        int s = t & 1;
        cp_wait_all();
        __syncthreads();
        /* issue next tile's loads */
        if (t + 1 < ntile) {
            const float* Ag2 = Ag + (t+1)*32;
            const float* Bg2 = Bg + (size_t)(t+1)*32*N;
            #pragma unroll
            for (int j = 0; j < 4; j++) apf[j] = *(const float4*)(Ag2 + 4*j);
            #pragma unroll
            for (int j = 0; j < 4; j++)
                cp16(&Bs[(s^1)*TILEW + (bkr + 8*j)*PADS + bn4],
                     Bg2 + (size_t)(8*j)*N);
            cp_commit();
        }
        /* compute on stage s */
        const uint32_t* Ast = As + s*TILEW;
        const float*    Bst = Bs + s*TILEW;
        #pragma unroll
        for (int ks = 0; ks < 4; ks++) {
            int kk = ks * 8;
            uint32_t af[4][4], bf[4][2];
            #pragma unroll
            for (int mt = 0; mt < 4; mt++) {
                int m0 = wm*64 + mt*16;
                af[mt][0] = Ast[(kk+qid  )*PADS + m0 + grp    ];
                af[mt][1] = Ast[(kk+qid  )*PADS + m0 + grp + 8];
                af[mt][2] = Ast[(kk+qid+4)*PADS + m0 + grp    ];
                af[mt][3] = Ast[(kk+qid+4)*PADS + m0 + grp + 8];
            }
            #pragma unroll
            for (int nt = 0; nt < 4; nt++) {
                int n0 = wn*32 + nt*8;
                bf[nt][0] = f2tf(Bst[(kk+qid  )*PADS + n0 + grp]);
                bf[nt][1] = f2tf(Bst[(kk+qid+4)*PADS + n0 + grp]);
            }
            #pragma unroll
            for (int mt = 0; mt < 4; mt++)
                #pragma unroll
                for (int nt = 0; nt < 4; nt++)
                    mma_tf32(acc[mt][nt], af[mt], bf[nt]);
        }
        /* store prefetched A into other stage (safe: nobody reads it now) */
        if (t + 1 < ntile) {
            uint32_t* Adst = As + (s^1)*TILEW;
            #pragma unroll
            for (int j = 0; j < 4; j++) {
                int kk = akb + 4*j;
                Adst[(kk+0)*PADS + am] = f2tf(apf[j].x);
                Adst[(kk+1)*PADS + am] = f2tf(apf[j].y);
                Adst[(kk+2)*PADS + am] = f2tf(apf[j].z);
                Adst[(kk+3)*PADS + am] = f2tf(apf[j].w);
            }
        }
    }

    /* epilogue */
    #pragma unroll
    for (int mt = 0; mt < 4; mt++) {
        int r0 = bm + wm*64 + mt*16 + grp;
        #pragma unroll
        for (int nt = 0; nt < 4; nt++) {
            int c0 = bn + wn*32 + nt*8 + qid*2;
            float b0 = bias[c0], b1 = bias[c0+1];
            float v0 = acc[mt][nt][0] + b0;
            float v1 = acc[mt][nt][1] + b1;
            float v2 = acc[mt][nt][2] + b0;
            float v3 = acc[mt][nt][3] + b1;
            if (RELU) {
                v0 = fmaxf(v0, 0.f); v1 = fmaxf(v1, 0.f);
                v2 = fmaxf(v2, 0.f); v3 = fmaxf(v3, 0.f);
            }
            *(float2*)&C[(size_t)r0*N + c0]     = make_float2(v0, v1);
            *(float2*)&C[(size_t)(r0+8)*N + c0] = make_float2(v2, v3);
        }
    }
}

__global__ __launch_bounds__(256, 2)
void gemm_tc(const float* __restrict__ A, const float* __restrict__ W,
             const float* __restrict__ bias, float* __restrict__ C,
             int M, int N, int K) {
    gemm_body<0>(A, W, bias, C, M, N, K);
}

__global__ __launch_bounds__(256, 2)
void gemm_tc_relu(const float* __restrict__ A, const float* __restrict__ W,
                  const float* __restrict__ bias, float* __restrict__ C,
                  int M, int N, int K) {
    gemm_body<1>(A, W, bias, C, M, N, K);
}

/* fused q/k/v: blockIdx.z selects weight/bias/output */
__global__ __launch_bounds__(256, 2)
void gemm_tc_qkv(const float* __restrict__ A,
                 const float* __restrict__ Wq, const float* __restrict__ Wk,
                 const float* __restrict__ Wv,
                 const float* __restrict__ bq, const float* __restrict__ bk,
                 const float* __restrict__ bv,
                 float* __restrict__ Cq, float* __restrict__ Ck,
                 float* __restrict__ Cv) {
    const float* W; const float* bi; float* C;
    if (blockIdx.z == 0)      { W = Wq; bi = bq; C = Cq; }
    else if (blockIdx.z == 1) { W = Wk; bi = bk; C = Ck; }
    else                      { W = Wv; bi = bv; C = Cv; }
    gemm_body<0>(A, W, bi, C, ROWS, DD, DD);
}

/* ------------------ attention: one block per (b,n,h), 128 threads ------ */
__global__ void attn_kernel(const float* __restrict__ Q,
                            const float* __restrict__ K,
                            const float* __restrict__ V,
                            float* __restrict__ O) {
    __shared__ float ks[TT][DH];
    __shared__ float vs[TT][DH];
    int bh = blockIdx.x;
    int h  = bh & (HH-1);
    int bn = bh >> 3;
    size_t base = (size_t)bn*TT*DD + h*DH;
    int tid = threadIdx.x;  /* 128: one query row each */

    const float4* kp = (const float4*)(K + base + (size_t)tid*DD);
    const float4* vp = (const float4*)(V + base + (size_t)tid*DD);
    float4* ksp = (float4*)&ks[tid][0];
    float4* vsp = (float4*)&vs[tid][0];
    #pragma unroll
    for (int j = 0; j < 4; j++) { ksp[j] = kp[j]; vsp[j] = vp[j]; }

    float qr[DH];
    const float4* qp = (const float4*)(Q + base + (size_t)tid*DD);
    #pragma unroll
    for (int j = 0; j < 4; j++) ((float4*)qr)[j] = qp[j];
    __syncthreads();

    float mx = -1e30f, lsum = 0.f;
    float acc[DH];
    #pragma unroll
    for (int d2 = 0; d2 < DH; d2++) acc[d2] = 0.f;

    for (int j = 0; j < TT; j++) {
        float s = 0.f;
        #pragma unroll
        for (int d2 = 0; d2 < DH; d2++) s += qr[d2]*ks[j][d2];
        s *= 0.25f;  /* 1/sqrt(16) */
        float mn = fmaxf(mx, s);
        float corr = __expf(mx - mn);
        float p = __expf(s - mn);
        lsum = lsum*corr + p;
        #pragma unroll
        for (int d2 = 0; d2 < DH; d2++) acc[d2] = acc[d2]*corr + p*vs[j][d2];
        mx = mn;
    }
    float inv = 1.f/lsum;
    float* op = O + base + (size_t)tid*DD;
    #pragma unroll
    for (int d2 = 0; d2 < DH; d2++) op[d2] = acc[d2]*inv;
}

/* ------------------ out = LayerNorm(A + Bv) * g + beta ------------------ */
__global__ void add_ln_kernel(const float* __restrict__ A,
                              const float* __restrict__ Bv,
                              const float* __restrict__ g,
                              const float* __restrict__ bet,
                              float* __restrict__ out) {
    int r = blockIdx.x;
    int tid = threadIdx.x;  /* 128 */
    float x = A[(size_t)r*DD + tid] + Bv[(size_t)r*DD + tid];
    float s = x, sq = x*x;
    #pragma unroll
    for (int o = 16; o > 0; o >>= 1) {
        s  += __shfl_xor_sync(0xffffffffu, s, o);
        sq += __shfl_xor_sync(0xffffffffu, sq, o);
    }
    __shared__ float ss[4], ssq[4];
    int w = tid >> 5, ln = tid & 31;
    if (ln == 0) { ss[w] = s; ssq[w] = sq; }
    __syncthreads();
    s  = ss[0]+ss[1]+ss[2]+ss[3];
    sq = ssq[0]+ssq[1]+ssq[2]+ssq[3];
    float m = s * (1.f/DD);
    float var = sq * (1.f/DD) - m*m;
    out[(size_t)r*DD + tid] = (x - m)*rsqrtf(var + EPSV)*g[tid] + bet[tid];
}

/* ------------------ s[b, t*NA+n] = dot(out_e row, x row) --------------- */
__global__ void dot_kernel() {
    int r  = blockIdx.x*8 + (threadIdx.x >> 5);
    int ln = threadIdx.x & 31;
    const float* a = g_oute + (size_t)r*DD;
    const float* c = g_x    + (size_t)r*DD;
    float s = 0.f;
    #pragma unroll
    for (int j = ln; j < DD; j += 32) s += a[j]*c[j];
    #pragma unroll
    for (int o = 16; o > 0; o >>= 1) s += __shfl_xor_sync(0xffffffffu, s, o);
    if (ln == 0) {
        int b = r / (NA*TT);
        int rem = r % (NA*TT);
        int n = rem >> 7;
        int t = rem & 127;
        g_s[b*NNODE + t*NA + n] = s;
    }
}

__global__ void zero_kernel() {
    int i = blockIdx.x*256 + threadIdx.x;
    if (i < BSZ*NNODE) g_gr[i] = 0.f;
}

/* ------------------ edge segment-sum via atomics ----------------------- */
__global__ void agg_kernel(const int* __restrict__ ei,
                           const float* __restrict__ ew) {
    int i = blockIdx.x*256 + threadIdx.x;
    if (i >= BSZ*EE) return;
    int b = i >> 16;
    int e = i & (EE-1);
    int src = ei[(size_t)b*2*EE + e];
    int dst = ei[(size_t)b*2*EE + EE + e];
    atomicAdd(&g_gr[b*NNODE + dst], ew[(size_t)b*EE + e] * g_s[b*NNODE + src]);
}

/* ------------------ global mean / rsqrt(var) --------------------------- */
__global__ void stats_kernel() {
    int tid = threadIdx.x;  /* 1024 */
    float s = 0.f, sq = 0.f;
    for (int i = tid; i < BSZ*NNODE; i += 1024) {
        float v = g_gr[i];
        s += v; sq += v*v;
    }
    #pragma unroll
    for (int o = 16; o > 0; o >>= 1) {
        s  += __shfl_xor_sync(0xffffffffu, s, o);
        sq += __shfl_xor_sync(0xffffffffu, sq, o);
    }
    __shared__ float ss[32], ssq[32];
    int w = tid >> 5, ln = tid & 31;
    if (ln == 0) { ss[w] = s; ssq[w] = sq; }
    __syncthreads();
    if (tid == 0) {
        float ts = 0.f, tq = 0.f;
        #pragma unroll
        for (int j = 0; j < 32; j++) { ts += ss[j]; tq += ssq[j]; }
        float m = ts / (float)(BSZ*NNODE);
        float var = tq / (float)(BSZ*NNODE) - m*m;
        g_stats[0] = m;
        g_stats[1] = rsqrtf(var + EPSV);
    }
}

/* ------------------ final: out[b,n,t,d] = bn(g)[b,t,n]*lw[d]+lb[d] ----- */
__global__ void final_kernel(const float* __restrict__ bng,
                             const float* __restrict__ bnb,
                             const float* __restrict__ lw,
                             const float* __restrict__ lb,
                             float* __restrict__ out) {
    int i = blockIdx.x*256 + threadIdx.x;
    if (i >= ROWS*DD) return;
    int d = i & 127;
    int r = i >> 7;
    int t = r & 127;
    int bn = r >> 7;
    int n = bn & 63;
    int b = bn >> 6;
    float gv = (g_gr[b*NNODE + t*NA + n] - g_stats[0]) * g_stats[1] * bng[0] + bnb[0];
    out[i] = gv * lw[d] + lb[d];
}

/* ---------------------------------------------------------------------- */
extern "C" void kernel_launch(void* const* d_in, const int* in_sizes, int n_in,
                              void* d_out, int out_size) {
    const float* ahf  = (const float*)d_in[0];
    const int*   ei   = (const int*)  d_in[1];
    const float* ew   = (const float*)d_in[2];
    const float* hw   = (const float*)d_in[3];
    const float* hb   = (const float*)d_in[4];
    const float* wq   = (const float*)d_in[5];
    const float* bq   = (const float*)d_in[6];
    const float* wk   = (const float*)d_in[7];
    const float* bk   = (const float*)d_in[8];
    const float* wv   = (const float*)d_in[9];
    const float* bv   = (const float*)d_in[10];
    const float* wo   = (const float*)d_in[11];
    const float* bo   = (const float*)d_in[12];
    const float* ln1g = (const float*)d_in[13];
    const float* ln1b = (const float*)d_in[14];
    const float* fw1  = (const float*)d_in[15];
    const float* fb1  = (const float*)d_in[16];
    const float* fw2  = (const float*)d_in[17];
    const float* fb2  = (const float*)d_in[18];
    const float* ln2g = (const float*)d_in[19];
    const float* ln2b = (const float*)d_in[20];
    const float* bng  = (const float*)d_in[21];
    const float* bnb  = (const float*)d_in[22];
    const float* lgw  = (const float*)d_in[23];
    const float* lgb  = (const float*)d_in[24];
    float* out = (float*)d_out;

    float *px, *poute, *pq, *pk, *pv, *pao, *ph1, *pff1, *ptmp;
    cudaGetSymbolAddress((void**)&px,    g_x);
    cudaGetSymbolAddress((void**)&poute, g_oute);
    cudaGetSymbolAddress((void**)&pq,    g_q);
    cudaGetSymbolAddress((void**)&pk,    g_k);
    cudaGetSymbolAddress((void**)&pv,    g_v);
    cudaGetSymbolAddress((void**)&pao,   g_ao);
    cudaGetSymbolAddress((void**)&ph1,   g_h1);
    cudaGetSymbolAddress((void**)&pff1,  g_ff1);
    cudaGetSymbolAddress((void**)&ptmp,  g_tmp);

    static int smem_set = 0;
    if (!smem_set) {
        cudaFuncSetAttribute(gemm_tc,
            cudaFuncAttributeMaxDynamicSharedMemorySize, SMEM_BYTES);
        cudaFuncSetAttribute(gemm_tc_relu,
            cudaFuncAttributeMaxDynamicSharedMemorySize, SMEM_BYTES);
        cudaFuncSetAttribute(gemm_tc_qkv,
            cudaFuncAttributeMaxDynamicSharedMemorySize, SMEM_BYTES);
        smem_set = 1;
    }

    embed_kernel<<<(ROWS*DD)/256, 256>>>(ahf, hw, hb);

    dim3 gqkv(DD/128, ROWS/128, 3);   /* (1, 256, 3) */
    dim3 gp(DD/128, ROWS/128);        /* (1, 256) */
    dim3 g1(DFF/128, ROWS/128);       /* (4, 256) */

    for (int l = 0; l < LL; l++) {
        const float* Wq = wq + (size_t)l*DD*DD;
        const float* Wk = wk + (size_t)l*DD*DD;
        const float* Wv = wv + (size_t)l*DD*DD;
        const float* Wo = wo + (size_t)l*DD*DD;
        gemm_tc_qkv<<<gqkv, 256, SMEM_BYTES>>>(poute, Wq, Wk, Wv,
                                   bq + l*DD, bk + l*DD, bv + l*DD,
                                   pq, pk, pv);
        attn_kernel<<<BSZ*NA*HH, 128>>>(pq, pk, pv, pao);
        gemm_tc<<<gp, 256, SMEM_BYTES>>>(pao, Wo, bo + l*DD, ptmp,
                                         ROWS, DD, DD);
        add_ln_kernel<<<ROWS, 128>>>(poute, ptmp, ln1g + l*DD, ln1b + l*DD, ph1);
        gemm_tc_relu<<<g1, 256, SMEM_BYTES>>>(ph1, fw1 + (size_t)l*DD*DFF,
                                  fb1 + l*DFF, pff1, ROWS, DFF, DD);
        gemm_tc<<<gp, 256, SMEM_BYTES>>>(pff1, fw2 + (size_t)l*DFF*DD,
                                  fb2 + l*DD, ptmp, ROWS, DD, DFF);
        add_ln_kernel<<<ROWS, 128>>>(ph1, ptmp, ln2g + l*DD, ln2b + l*DD, poute);
    }

    dot_kernel<<<ROWS/8, 256>>>();
    zero_kernel<<<(BSZ*NNODE + 255)/256, 256>>>();
    agg_kernel<<<(BSZ*EE + 255)/256, 256>>>(ei, ew);
    stats_kernel<<<1, 1024>>>();
    final_kernel<<<(ROWS*DD)/256, 256>>>(bng, bnb, lgw, lgb, out);
}

// round 13
// speedup vs baseline: 2.3843x; 1.2937x over previous
#include <cuda_runtime.h>
#include <cuda_fp16.h>
#include <math.h>
#include <stdint.h>

#define BSZ 4
#define NA 64
#define TT 128
#define DD 128
#define HH 8
#define DH 16
#define LL 3
#define DFF 512
#define EE 65536
#define NNODE (TT*NA)          /* 8192 */
#define ROWS (BSZ*NA*TT)       /* 32768 */
#define EPSV 1e-5f

#define WT_LAYER 196608        /* fp16 elems per layer of transposed weights */
#define WT_W1 65536
#define WT_W2 131072

/* ------------------ scratch (static device globals, no allocs) -------- */
__device__ float g_x[ROWS*DD];
__device__ float g_oute[ROWS*DD];
__device__ float g_h1[ROWS*DD];
__device__ float g_tmp[ROWS*DD];
__device__ float g_s[BSZ*NNODE];
__device__ float g_gr[BSZ*NNODE];
__device__ float g_stats[2];
__device__ __align__(16) __half g_wt[3*WT_LAYER];   /* W^T fp16, K-major */
__device__ __align__(16) __half g_oute16[ROWS*DD];
__device__ __align__(16) __half g_q16[ROWS*DD];
__device__ __align__(16) __half g_k16[ROWS*DD];
__device__ __align__(16) __half g_v16[ROWS*DD];
__device__ __align__(16) __half g_ao16[ROWS*DD];
__device__ __align__(16) __half g_h116[ROWS*DD];
__device__ __align__(16) __half g_ff116[ROWS*DFF];

/* ------------------ embed: x = ahf @ hist_w + hist_b ; out_e = x + PE -- */
__global__ void embed_kernel(const float* __restrict__ ahf,
                             const float* __restrict__ hw,
                             const float* __restrict__ hb) {
    int i = blockIdx.x * 256 + threadIdx.x;
    if (i >= ROWS*DD) return;
    int r = i >> 7;
    int d = i & 127;
    int t = r & (TT-1);
    float a0 = ahf[r*3+0], a1 = ahf[r*3+1], a2 = ahf[r*3+2];
    float xv = a0*hw[d] + a1*hw[DD+d] + a2*hw[2*DD+d] + hb[d];
    g_x[i] = xv;
    int ii = (d >> 1) * 2;
    float freq = __expf(-logf(10000.0f) * (float)ii / (float)DD);
    float ang = (float)t * freq;
    float pe = (d & 1) ? cosf(ang) : sinf(ang);
    float ov = xv + pe;
    g_oute[i] = ov;
    g_oute16[i] = __float2half(ov);
}

/* ------------------ weight transpose+cvt: g_wt = fp16(W^T) ------------- */
__global__ void tp_kernel(const float* __restrict__ wq, const float* __restrict__ wk,
                          const float* __restrict__ wv, const float* __restrict__ wo,
                          const float* __restrict__ fw1, const float* __restrict__ fw2) {
    int i = blockIdx.x*256 + threadIdx.x;
    if (i >= 3*WT_LAYER) return;
    int l = i / WT_LAYER;
    int r = i % WT_LAYER;
    float v;
    if (r < WT_W1) {
        int mat = r >> 14, e = r & 16383;
        int n = e >> 7, k = e & 127;
        const float* w = (mat==0) ? wq : (mat==1) ? wk : (mat==2) ? wv : wo;
        v = w[(size_t)l*16384 + k*128 + n];
    } else if (r < WT_W2) {
        int e = r - WT_W1;          /* n*128+k, n<512 k<128 */
        int n = e >> 7, k = e & 127;
        v = fw1[(size_t)l*65536 + k*512 + n];
    } else {
        int e = r - WT_W2;          /* n*512+k, n<128 k<512 */
        int n = e >> 9, k = e & 511;
        v = fw2[(size_t)l*65536 + k*128 + n];
    }
    g_wt[i] = __float2half(v);
}

/* ------------------ asm helpers ----------------------------------------- */
__device__ __forceinline__ uint32_t s2u(const void* p) {
    return (uint32_t)__cvta_generic_to_shared(p);
}
__device__ __forceinline__ void cp16(uint32_t smem_dst, const void* gmem_src) {
    asm volatile("cp.async.cg.shared.global [%0], [%1], 16;\n"
                 :: "r"(smem_dst), "l"(gmem_src));
}
__device__ __forceinline__ void cp_commit() {
    asm volatile("cp.async.commit_group;\n");
}
__device__ __forceinline__ void cp_wait_all() {
    asm volatile("cp.async.wait_group 0;\n");
}
__device__ __forceinline__ void ldsm4(uint32_t& r0, uint32_t& r1,
                                      uint32_t& r2, uint32_t& r3, uint32_t a) {
    asm volatile("ldmatrix.sync.aligned.m8n8.x4.shared.b16 {%0,%1,%2,%3}, [%4];"
                 : "=r"(r0), "=r"(r1), "=r"(r2), "=r"(r3) : "r"(a));
}
__device__ __forceinline__ void mma_f16(float* c, const uint32_t* a,
                                        const uint32_t* b) {
    asm volatile(
        "mma.sync.aligned.m16n8k16.row.col.f32.f16.f16.f32 "
        "{%0,%1,%2,%3}, {%4,%5,%6,%7}, {%8,%9}, {%0,%1,%2,%3};\n"
        : "+f"(c[0]), "+f"(c[1]), "+f"(c[2]), "+f"(c[3])
        : "r"(a[0]), "r"(a[1]), "r"(a[2]), "r"(a[3]),
          "r"(b[0]), "r"(b[1]));
}

/* ------------------ fp16 HMMA GEMM: C = A(MxK)@W(KxN)+bias --------------
   128x128 CTA tile, BK=64 (128B fp16 rows, SW128 swizzle), 256 threads,
   8 warps (2x4), warp tile 64x32 = 4x4 m16n8k16. A and B both fp16 in
   gmem (B = pretransposed W^T[n][k]); cp.async double-buffered.          */
template<int RELU, int OUT16>
__device__ __forceinline__ void gemm_body(const __half* __restrict__ A,
                                          const __half* __restrict__ Bt,
                                          const float* __restrict__ bias,
                                          float* __restrict__ C32,
                                          __half* __restrict__ C16,
                                          int N, int K, int bm, int bn) {
    __shared__ __align__(16) __half As[2][128*64];
    __shared__ __align__(16) __half Bs[2][128*64];

    int tid  = threadIdx.x;
    int lane = tid & 31;
    int wid  = tid >> 5;
    int wm   = wid >> 2;    /* 0..1 -> 64-row slab */
    int wn   = wid & 3;     /* 0..3 -> 32-col slab */

    float acc[4][4][4];
    #pragma unroll
    for (int mt = 0; mt < 4; mt++)
        #pragma unroll
        for (int nt = 0; nt < 4; nt++)
            #pragma unroll
            for (int i = 0; i < 4; i++) acc[mt][nt][i] = 0.f;

    /* loader mapping: 2 threads per 128B row, 4x16B chunks each */
    int m  = tid & 127;
    int hf = tid >> 7;                 /* 0/1 -> which 64B half */
    uint32_t xm = (uint32_t)((m & 7) << 4);
    const __half* Ag = A  + (size_t)(bm + m)*K + hf*32;
    const __half* Bg = Bt + (size_t)(bn + m)*K + hf*32;
    uint32_t aS0 = s2u(&As[0][0]), bS0 = s2u(&Bs[0][0]);
    uint32_t arow = (uint32_t)(m*128);

    /* fragment lane mapping */
    int r8 = lane & 7, q = lane >> 3;
    uint32_t axor = (uint32_t)(r8 << 4);

    int ntile = K >> 6;

    /* prologue: stage 0, tile 0 */
    #pragma unroll
    for (int j = 0; j < 4; j++) {
        uint32_t colb = (uint32_t)(hf*64 + j*16);
        cp16(aS0 + arow + (colb ^ xm), Ag + j*8);
        cp16(bS0 + arow + (colb ^ xm), Bg + j*8);
    }
    cp_commit();

    for (int t = 0; t < ntile; t++) {
        int s = t & 1;
        cp_wait_all();
        __syncthreads();
        if (t + 1 < ntile) {
            const __half* Ag2 = Ag + (t+1)*64;
            const __half* Bg2 = Bg + (t+1)*64;
            uint32_t aS = aS0 + (s^1)*16384, bS = bS0 + (s^1)*16384;
            #pragma unroll
            for (int j = 0; j < 4; j++) {
                uint32_t colb = (uint32_t)(hf*64 + j*16);
                cp16(aS + arow + (colb ^ xm), Ag2 + j*8);
                cp16(bS + arow + (colb ^ xm), Bg2 + j*8);
            }
            cp_commit();
        }
        /* compute stage s */
        uint32_t aB = aS0 + s*16384, bB = bS0 + s*16384;
        uint32_t rowA[4], rowB[2];
        #pragma unroll
        for (int mt = 0; mt < 4; mt++)
            rowA[mt] = aB + (uint32_t)((wm*64 + mt*16 + r8 + (q&1)*8) * 128);
        #pragma unroll
        for (int p = 0; p < 2; p++)
            rowB[p] = bB + (uint32_t)((wn*32 + p*16 + (q>>1)*8 + r8) * 128);
        #pragma unroll
        for (int ks = 0; ks < 4; ks++) {
            uint32_t colA = ((uint32_t)(ks*32 + (q>>1)*16)) ^ axor;
            uint32_t colB = ((uint32_t)(ks*32 + (q&1)*16)) ^ axor;
            uint32_t af[4][4], bf[4][2];
            #pragma unroll
            for (int mt = 0; mt < 4; mt++)
                ldsm4(af[mt][0], af[mt][1], af[mt][2], af[mt][3],
                      rowA[mt] + colA);
            #pragma unroll
            for (int p = 0; p < 2; p++)
                ldsm4(bf[2*p][0], bf[2*p][1], bf[2*p+1][0], bf[2*p+1][1],
                      rowB[p] + colB);
            #pragma unroll
            for (int mt = 0; mt < 4; mt++)
                #pragma unroll
                for (int nt = 0; nt < 4; nt++)
                    mma_f16(acc[mt][nt], af[mt], bf[nt]);
        }
    }

    /* epilogue */
    int grp = lane >> 2, qid = lane & 3;
    #pragma unroll
    for (int mt = 0; mt < 4; mt++) {
        int r0 = bm + wm*64 + mt*16 + grp;
        #pragma unroll
        for (int nt = 0; nt < 4; nt++) {
            int c0 = bn + wn*32 + nt*8 + qid*2;
            float b0 = bias[c0], b1 = bias[c0+1];
            float v0 = acc[mt][nt][0] + b0;
            float v1 = acc[mt][nt][1] + b1;
            float v2 = acc[mt][nt][2] + b0;
            float v3 = acc[mt][nt][3] + b1;
            if (RELU) {
                v0 = fmaxf(v0, 0.f); v1 = fmaxf(v1, 0.f);
                v2 = fmaxf(v2, 0.f); v3 = fmaxf(v3, 0.f);
            }
            if (OUT16) {
                *(__half2*)&C16[(size_t)r0*N + c0] = __floats2half2_rn(v0, v1);
                *(__half2*)&C16[(size_t)(r0+8)*N + c0] = __floats2half2_rn(v2, v3);
            } else {
                *(float2*)&C32[(size_t)r0*N + c0]     = make_float2(v0, v1);
                *(float2*)&C32[(size_t)(r0+8)*N + c0] = make_float2(v2, v3);
            }
        }
    }
}

__global__ __launch_bounds__(256, 2)
void gemm_f32(const __half* __restrict__ A, const __half* __restrict__ Bt,
              const float* __restrict__ bias, float* __restrict__ C,
              int N, int K) {
    gemm_body<0,0>(A, Bt, bias, C, (__half*)0, N, K,
                   blockIdx.y*128, blockIdx.x*128);
}

__global__ __launch_bounds__(256, 2)
void gemm_h16_relu(const __half* __restrict__ A, const __half* __restrict__ Bt,
                   const float* __restrict__ bias, __half* __restrict__ C,
                   int N, int K) {
    gemm_body<1,1>(A, Bt, bias, (float*)0, C, N, K,
                   blockIdx.y*128, blockIdx.x*128);
}

/* fused q/k/v: blockIdx.z selects weight/bias/output, fp16 out */
__global__ __launch_bounds__(256, 2)
void gemm_qkv(const __half* __restrict__ A, const __half* __restrict__ BtL,
              const float* __restrict__ bq, const float* __restrict__ bk,
              const float* __restrict__ bv,
              __half* __restrict__ Cq, __half* __restrict__ Ck,
              __half* __restrict__ Cv) {
    const __half* Bt; const float* bi; __half* C;
    if (blockIdx.z == 0)      { Bt = BtL;          bi = bq; C = Cq; }
    else if (blockIdx.z == 1) { Bt = BtL + 16384;  bi = bk; C = Ck; }
    else                      { Bt = BtL + 32768;  bi = bv; C = Cv; }
    gemm_body<0,1>(A, Bt, bi, (float*)0, C, DD, DD, blockIdx.y*128, 0);
}

/* ------------------ attention: one block per (b,n,h), 128 threads ------
   fp16 q/k/v in, fp16 out (feeds o-proj GEMM); fp32 math inside.        */
__global__ void attn_kernel(const __half* __restrict__ Q,
                            const __half* __restrict__ K,
                            const __half* __restrict__ V,
                            __half* __restrict__ O) {
    __shared__ float ks[TT][DH];
    __shared__ float vs[TT][DH];
    int bh = blockIdx.x;
    int h  = bh & (HH-1);
    int bn = bh >> 3;
    size_t base = (size_t)bn*TT*DD + h*DH;
    int tid = threadIdx.x;  /* 128: one query row each */

    const uint4* kp = (const uint4*)(K + base + (size_t)tid*DD);
    const uint4* vp = (const uint4*)(V + base + (size_t)tid*DD);
    const uint4* qp = (const uint4*)(Q + base + (size_t)tid*DD);
    float qr[DH];
    #pragma unroll
    for (int j = 0; j < 2; j++) {   /* 2 x uint4 = 16 halves */
        uint4 ku = kp[j], vu = vp[j], qu = qp[j];
        const __half2* kh = (const __half2*)&ku;
        const __half2* vh = (const __half2*)&vu;
        const __half2* qh = (const __half2*)&qu;
        #pragma unroll
        for (int i = 0; i < 4; i++) {
            float2 kf = __half22float2(kh[i]);
            float2 vf = __half22float2(vh[i]);
            float2 qf = __half22float2(qh[i]);
            ks[tid][j*8 + i*2]     = kf.x;
            ks[tid][j*8 + i*2 + 1] = kf.y;
            vs[tid][j*8 + i*2]     = vf.x;
            vs[tid][j*8 + i*2 + 1] = vf.y;
            qr[j*8 + i*2]     = qf.x;
            qr[j*8 + i*2 + 1] = qf.y;
        }
    }
    __syncthreads();

    float mx = -1e30f, lsum = 0.f;
    float acc[DH];
    #pragma unroll
    for (int d2 = 0; d2 < DH; d2++) acc[d2] = 0.f;

    for (int j = 0; j < TT; j++) {
        float s = 0.f;
        #pragma unroll
        for (int d2 = 0; d2 < DH; d2++) s += qr[d2]*ks[j][d2];
        s *= 0.25f;  /* 1/sqrt(16) */
        float mn = fmaxf(mx, s);
        float corr = __expf(mx - mn);
        float p = __expf(s - mn);
        lsum = lsum*corr + p;
        #pragma unroll
        for (int d2 = 0; d2 < DH; d2++) acc[d2] = acc[d2]*corr + p*vs[j][d2];
        mx = mn;
    }
    float inv = 1.f/lsum;
    __half2* op = (__half2*)(O + base + (size_t)tid*DD);
    #pragma unroll
    for (int d2 = 0; d2 < DH; d2 += 2)
        op[d2/2] = __floats2half2_rn(acc[d2]*inv, acc[d2+1]*inv);
}

/* ------------------ out = LayerNorm(A + Bv) * g + beta (fp32 + fp16) --- */
__global__ void add_ln_kernel(const float* __restrict__ A,
                              const float* __restrict__ Bv,
                              const float* __restrict__ g,
                              const float* __restrict__ bet,
                              float* __restrict__ out,
                              __half* __restrict__ out16) {
    int r = blockIdx.x;
    int tid = threadIdx.x;  /* 128 */
    float x = A[(size_t)r*DD + tid] + Bv[(size_t)r*DD + tid];
    float s = x, sq = x*x;
    #pragma unroll
    for (int o = 16; o > 0; o >>= 1) {
        s  += __shfl_xor_sync(0xffffffffu, s, o);
        sq += __shfl_xor_sync(0xffffffffu, sq, o);
    }
    __shared__ float ss[4], ssq[4];
    int w = tid >> 5, ln = tid & 31;
    if (ln == 0) { ss[w] = s; ssq[w] = sq; }
    __syncthreads();
    s  = ss[0]+ss[1]+ss[2]+ss[3];
    sq = ssq[0]+ssq[1]+ssq[2]+ssq[3];
    float m = s * (1.f/DD);
    float var = sq * (1.f/DD) - m*m;
    float o = (x - m)*rsqrtf(var + EPSV)*g[tid] + bet[tid];
    out[(size_t)r*DD + tid] = o;
    out16[(size_t)r*DD + tid] = __float2half(o);
}

/* ------------------ s[b, t*NA+n] = dot(out_e row, x row) --------------- */
__global__ void dot_kernel() {
    int r  = blockIdx.x*8 + (threadIdx.x >> 5);
    int ln = threadIdx.x & 31;
    const float* a = g_oute + (size_t)r*DD;
    const float* c = g_x    + (size_t)r*DD;
    float s = 0.f;
    #pragma unroll
    for (int j = ln; j < DD; j += 32) s += a[j]*c[j];
    #pragma unroll
    for (int o = 16; o > 0; o >>= 1) s += __shfl_xor_sync(0xffffffffu, s, o);
    if (ln == 0) {
        int b = r / (NA*TT);
        int rem = r % (NA*TT);
        int n = rem >> 7;
        int t = rem & 127;
        g_s[b*NNODE + t*NA + n] = s;
    }
}

__global__ void zero_kernel() {
    int i = blockIdx.x*256 + threadIdx.x;
    if (i < BSZ*NNODE) g_gr[i] = 0.f;
}

/* ------------------ edge segment-sum via atomics ----------------------- */
__global__ void agg_kernel(const int* __restrict__ ei,
                           const float* __restrict__ ew) {
    int i = blockIdx.x*256 + threadIdx.x;
    if (i >= BSZ*EE) return;
    int b = i >> 16;
    int e = i & (EE-1);
    int src = ei[(size_t)b*2*EE + e];
    int dst = ei[(size_t)b*2*EE + EE + e];
    atomicAdd(&g_gr[b*NNODE + dst], ew[(size_t)b*EE + e] * g_s[b*NNODE + src]);
}

/* ------------------ global mean / rsqrt(var) --------------------------- */
__global__ void stats_kernel() {
    int tid = threadIdx.x;  /* 1024 */
    float s = 0.f, sq = 0.f;
    for (int i = tid; i < BSZ*NNODE; i += 1024) {
        float v = g_gr[i];
        s += v; sq += v*v;
    }
    #pragma unroll
    for (int o = 16; o > 0; o >>= 1) {
        s  += __shfl_xor_sync(0xffffffffu, s, o);
        sq += __shfl_xor_sync(0xffffffffu, sq, o);
    }
    __shared__ float ss[32], ssq[32];
    int w = tid >> 5, ln = tid & 31;
    if (ln == 0) { ss[w] = s; ssq[w] = sq; }
    __syncthreads();
    if (tid == 0) {
        float ts = 0.f, tq = 0.f;
        #pragma unroll
        for (int j = 0; j < 32; j++) { ts += ss[j]; tq += ssq[j]; }
        float m = ts / (float)(BSZ*NNODE);
        float var = tq / (float)(BSZ*NNODE) - m*m;
        g_stats[0] = m;
        g_stats[1] = rsqrtf(var + EPSV);
    }
}

/* ------------------ final: out[b,n,t,d] = bn(g)[b,t,n]*lw[d]+lb[d] ----- */
__global__ void final_kernel(const float* __restrict__ bng,
                             const float* __restrict__ bnb,
                             const float* __restrict__ lw,
                             const float* __restrict__ lb,
                             float* __restrict__ out) {
    int i = blockIdx.x*256 + threadIdx.x;
    if (i >= ROWS*DD) return;
    int d = i & 127;
    int r = i >> 7;
    int t = r & 127;
    int bn = r >> 7;
    int n = bn & 63;
    int b = bn >> 6;
    float gv = (g_gr[b*NNODE + t*NA + n] - g_stats[0]) * g_stats[1] * bng[0] + bnb[0];
    out[i] = gv * lw[d] + lb[d];
}

/* ---------------------------------------------------------------------- */
extern "C" void kernel_launch(void* const* d_in, const int* in_sizes, int n_in,
                              void* d_out, int out_size) {
    const float* ahf  = (const float*)d_in[0];
    const int*   ei   = (const int*)  d_in[1];
    const float* ew   = (const float*)d_in[2];
    const float* hw   = (const float*)d_in[3];
    const float* hb   = (const float*)d_in[4];
    const float* wq   = (const float*)d_in[5];
    const float* bq   = (const float*)d_in[6];
    const float* wk   = (const float*)d_in[7];
    const float* bk   = (const float*)d_in[8];
    const float* wv   = (const float*)d_in[9];
    const float* bv   = (const float*)d_in[10];
    const float* wo   = (const float*)d_in[11];
    const float* bo   = (const float*)d_in[12];
    const float* ln1g = (const float*)d_in[13];
    const float* ln1b = (const float*)d_in[14];
    const float* fw1  = (const float*)d_in[15];
    const float* fb1  = (const float*)d_in[16];
    const float* fw2  = (const float*)d_in[17];
    const float* fb2  = (const float*)d_in[18];
    const float* ln2g = (const float*)d_in[19];
    const float* ln2b = (const float*)d_in[20];
    const float* bng  = (const float*)d_in[21];
    const float* bnb  = (const float*)d_in[22];
    const float* lgw  = (const float*)d_in[23];
    const float* lgb  = (const float*)d_in[24];
    float* out = (float*)d_out;

    float *poute, *ph1, *ptmp;
    __half *pwt, *poute16, *pq16, *pk16, *pv16, *pao16, *ph116, *pff116;
    cudaGetSymbolAddress((void**)&poute,   g_oute);
    cudaGetSymbolAddress((void**)&ph1,     g_h1);
    cudaGetSymbolAddress((void**)&ptmp,    g_tmp);
    cudaGetSymbolAddress((void**)&pwt,     g_wt);
    cudaGetSymbolAddress((void**)&poute16, g_oute16);
    cudaGetSymbolAddress((void**)&pq16,    g_q16);
    cudaGetSymbolAddress((void**)&pk16,    g_k16);
    cudaGetSymbolAddress((void**)&pv16,    g_v16);
    cudaGetSymbolAddress((void**)&pao16,   g_ao16);
    cudaGetSymbolAddress((void**)&ph116,   g_h116);
    cudaGetSymbolAddress((void**)&pff116,  g_ff116);

    tp_kernel<<<(3*WT_LAYER + 255)/256, 256>>>(wq, wk, wv, wo, fw1, fw2);
    embed_kernel<<<(ROWS*DD)/256, 256>>>(ahf, hw, hb);

    dim3 gqkv(1, ROWS/128, 3);    /* (1, 256, 3) */
    dim3 gp(1, ROWS/128);         /* (1, 256) */
    dim3 g1(DFF/128, ROWS/128);   /* (4, 256) */

    for (int l = 0; l < LL; l++) {
        const __half* WtL = pwt + (size_t)l*WT_LAYER;
        gemm_qkv<<<gqkv, 256>>>(poute16, WtL,
                                bq + l*DD, bk + l*DD, bv + l*DD,
                                pq16, pk16, pv16);
        attn_kernel<<<BSZ*NA*HH, 128>>>(pq16, pk16, pv16, pao16);
        gemm_f32<<<gp, 256>>>(pao16, WtL + 49152, bo + l*DD, ptmp, DD, DD);
        add_ln_kernel<<<ROWS, 128>>>(poute, ptmp, ln1g + l*DD, ln1b + l*DD,
                                     ph1, ph116);
        gemm_h16_relu<<<g1, 256>>>(ph116, WtL + WT_W1, fb1 + l*DFF,
                                   pff116, DFF, DD);
        gemm_f32<<<gp, 256>>>(pff116, WtL + WT_W2, fb2 + l*DD, ptmp, DD, DFF);
        add_ln_kernel<<<ROWS, 128>>>(ph1, ptmp, ln2g + l*DD, ln2b + l*DD,
                                     poute, poute16);
    }

    dot_kernel<<<ROWS/8, 256>>>();
    zero_kernel<<<(BSZ*NNODE + 255)/256, 256>>>();
    agg_kernel<<<(BSZ*EE + 255)/256, 256>>>(ei, ew);
    stats_kernel<<<1, 1024>>>();
    final_kernel<<<(ROWS*DD)/256, 256>>>(bng, bnb, lgw, lgb, out);
}

// round 17
// speedup vs baseline: 3.5827x; 1.5026x over previous
#include <cuda_runtime.h>
#include <cuda_fp16.h>
#include <math.h>
#include <stdint.h>

#define BSZ 4
#define NA 64
#define TT 128
#define DD 128
#define HH 8
#define DH 16
#define LL 3
#define DFF 512
#define EE 65536
#define NNODE (TT*NA)          /* 8192 */
#define ROWS (BSZ*NA*TT)       /* 32768 */
#define EPSV 1e-5f

#define WT_LAYER 196608        /* fp16 elems per layer of transposed weights */
#define WT_W1 65536
#define WT_W2 131072

#define ATT_PAD 136                    /* halves per smem row */
#define ATT_TB  (128*ATT_PAD)          /* halves per tensor */
#define ATT_SMEM (3*ATT_TB*2)          /* 104448 bytes */
#define SC2 0.360673760222f            /* 0.25 * log2(e) */

/* ------------------ scratch (static device globals, no allocs) -------- */
__device__ float g_x[ROWS*DD];
__device__ float g_oute[ROWS*DD];
__device__ float g_h1[ROWS*DD];
__device__ float g_tmp[ROWS*DD];
__device__ float g_s[BSZ*NNODE];
__device__ float g_gr[BSZ*NNODE];
__device__ float g_stats[2];
__device__ __align__(16) __half g_wt[3*WT_LAYER];   /* W^T fp16, K-major */
__device__ __align__(16) __half g_oute16[ROWS*DD];
__device__ __align__(16) __half g_q16[ROWS*DD];
__device__ __align__(16) __half g_k16[ROWS*DD];
__device__ __align__(16) __half g_v16[ROWS*DD];
__device__ __align__(16) __half g_ao16[ROWS*DD];
__device__ __align__(16) __half g_h116[ROWS*DD];
__device__ __align__(16) __half g_ff116[ROWS*DFF];

/* ------------------ embed: x = ahf @ hist_w + hist_b ; out_e = x + PE -- */
__global__ void embed_kernel(const float* __restrict__ ahf,
                             const float* __restrict__ hw,
                             const float* __restrict__ hb) {
    int i = blockIdx.x * 256 + threadIdx.x;
    if (i >= ROWS*DD) return;
    int r = i >> 7;
    int d = i & 127;
    int t = r & (TT-1);
    float a0 = ahf[r*3+0], a1 = ahf[r*3+1], a2 = ahf[r*3+2];
    float xv = a0*hw[d] + a1*hw[DD+d] + a2*hw[2*DD+d] + hb[d];
    g_x[i] = xv;
    int ii = (d >> 1) * 2;
    float freq = __expf(-logf(10000.0f) * (float)ii / (float)DD);
    float ang = (float)t * freq;
    float pe = (d & 1) ? cosf(ang) : sinf(ang);
    float ov = xv + pe;
    g_oute[i] = ov;
    g_oute16[i] = __float2half(ov);
}

/* ------------------ weight transpose+cvt: g_wt = fp16(W^T) ------------- */
__global__ void tp_kernel(const float* __restrict__ wq, const float* __restrict__ wk,
                          const float* __restrict__ wv, const float* __restrict__ wo,
                          const float* __restrict__ fw1, const float* __restrict__ fw2) {
    int i = blockIdx.x*256 + threadIdx.x;
    if (i >= 3*WT_LAYER) return;
    int l = i / WT_LAYER;
    int r = i % WT_LAYER;
    float v;
    if (r < WT_W1) {
        int mat = r >> 14, e = r & 16383;
        int n = e >> 7, k = e & 127;
        const float* w = (mat==0) ? wq : (mat==1) ? wk : (mat==2) ? wv : wo;
        v = w[(size_t)l*16384 + k*128 + n];
    } else if (r < WT_W2) {
        int e = r - WT_W1;          /* n*128+k, n<512 k<128 */
        int n = e >> 7, k = e & 127;
        v = fw1[(size_t)l*65536 + k*512 + n];
    } else {
        int e = r - WT_W2;          /* n*512+k, n<128 k<512 */
        int n = e >> 9, k = e & 511;
        v = fw2[(size_t)l*65536 + k*128 + n];
    }
    g_wt[i] = __float2half(v);
}

/* ------------------ asm helpers ----------------------------------------- */
__device__ __forceinline__ uint32_t s2u(const void* p) {
    return (uint32_t)__cvta_generic_to_shared(p);
}
__device__ __forceinline__ uint32_t h2u(__half2 h) {
    return *reinterpret_cast<uint32_t*>(&h);
}
__device__ __forceinline__ void cp16(uint32_t smem_dst, const void* gmem_src) {
    asm volatile("cp.async.cg.shared.global [%0], [%1], 16;\n"
                 :: "r"(smem_dst), "l"(gmem_src));
}
__device__ __forceinline__ void cp_commit() {
    asm volatile("cp.async.commit_group;\n");
}
__device__ __forceinline__ void cp_wait_all() {
    asm volatile("cp.async.wait_group 0;\n");
}
__device__ __forceinline__ void ldsm4(uint32_t& r0, uint32_t& r1,
                                      uint32_t& r2, uint32_t& r3, uint32_t a) {
    asm volatile("ldmatrix.sync.aligned.m8n8.x4.shared.b16 {%0,%1,%2,%3}, [%4];"
                 : "=r"(r0), "=r"(r1), "=r"(r2), "=r"(r3) : "r"(a));
}
__device__ __forceinline__ void ldsm4t(uint32_t& r0, uint32_t& r1,
                                       uint32_t& r2, uint32_t& r3, uint32_t a) {
    asm volatile("ldmatrix.sync.aligned.m8n8.x4.trans.shared.b16 {%0,%1,%2,%3}, [%4];"
                 : "=r"(r0), "=r"(r1), "=r"(r2), "=r"(r3) : "r"(a));
}
__device__ __forceinline__ void mma_f16(float* c, const uint32_t* a,
                                        const uint32_t* b) {
    asm volatile(
        "mma.sync.aligned.m16n8k16.row.col.f32.f16.f16.f32 "
        "{%0,%1,%2,%3}, {%4,%5,%6,%7}, {%8,%9}, {%0,%1,%2,%3};\n"
        : "+f"(c[0]), "+f"(c[1]), "+f"(c[2]), "+f"(c[3])
        : "r"(a[0]), "r"(a[1]), "r"(a[2]), "r"(a[3]),
          "r"(b[0]), "r"(b[1]));
}
__device__ __forceinline__ float ex2f(float x) {
    float y;
    asm("ex2.approx.ftz.f32 %0, %1;" : "=f"(y) : "f"(x));
    return y;
}

/* ------------------ fp16 HMMA GEMM: C = A(MxK)@W(KxN)+bias --------------
   128x128 CTA tile, BK=64 (128B fp16 rows, SW128 swizzle), 256 threads,
   8 warps (2x4), warp tile 64x32 = 4x4 m16n8k16. A and B both fp16 in
   gmem (B = pretransposed W^T[n][k]); cp.async double-buffered.          */
template<int RELU, int OUT16>
__device__ __forceinline__ void gemm_body(const __half* __restrict__ A,
                                          const __half* __restrict__ Bt,
                                          const float* __restrict__ bias,
                                          float* __restrict__ C32,
                                          __half* __restrict__ C16,
                                          int N, int K, int bm, int bn) {
    __shared__ __align__(16) __half As[2][128*64];
    __shared__ __align__(16) __half Bs[2][128*64];

    int tid  = threadIdx.x;
    int lane = tid & 31;
    int wid  = tid >> 5;
    int wm   = wid >> 2;    /* 0..1 -> 64-row slab */
    int wn   = wid & 3;     /* 0..3 -> 32-col slab */

    float acc[4][4][4];
    #pragma unroll
    for (int mt = 0; mt < 4; mt++)
        #pragma unroll
        for (int nt = 0; nt < 4; nt++)
            #pragma unroll
            for (int i = 0; i < 4; i++) acc[mt][nt][i] = 0.f;

    /* loader mapping: 2 threads per 128B row, 4x16B chunks each */
    int m  = tid & 127;
    int hf = tid >> 7;                 /* 0/1 -> which 64B half */
    uint32_t xm = (uint32_t)((m & 7) << 4);
    const __half* Ag = A  + (size_t)(bm + m)*K + hf*32;
    const __half* Bg = Bt + (size_t)(bn + m)*K + hf*32;
    uint32_t aS0 = s2u(&As[0][0]), bS0 = s2u(&Bs[0][0]);
    uint32_t arow = (uint32_t)(m*128);

    /* fragment lane mapping */
    int r8 = lane & 7, q = lane >> 3;
    uint32_t axor = (uint32_t)(r8 << 4);

    int ntile = K >> 6;

    /* prologue: stage 0, tile 0 */
    #pragma unroll
    for (int j = 0; j < 4; j++) {
        uint32_t colb = (uint32_t)(hf*64 + j*16);
        cp16(aS0 + arow + (colb ^ xm), Ag + j*8);
        cp16(bS0 + arow + (colb ^ xm), Bg + j*8);
    }
    cp_commit();

    for (int t = 0; t < ntile; t++) {
        int s = t & 1;
        cp_wait_all();
        __syncthreads();
        if (t + 1 < ntile) {
            const __half* Ag2 = Ag + (t+1)*64;
            const __half* Bg2 = Bg + (t+1)*64;
            uint32_t aS = aS0 + (s^1)*16384, bS = bS0 + (s^1)*16384;
            #pragma unroll
            for (int j = 0; j < 4; j++) {
                uint32_t colb = (uint32_t)(hf*64 + j*16);
                cp16(aS + arow + (colb ^ xm), Ag2 + j*8);
                cp16(bS + arow + (colb ^ xm), Bg2 + j*8);
            }
            cp_commit();
        }
        /* compute stage s */
        uint32_t aB = aS0 + s*16384, bB = bS0 + s*16384;
        uint32_t rowA[4], rowB[2];
        #pragma unroll
        for (int mt = 0; mt < 4; mt++)
            rowA[mt] = aB + (uint32_t)((wm*64 + mt*16 + r8 + (q&1)*8) * 128);
        #pragma unroll
        for (int p = 0; p < 2; p++)
            rowB[p] = bB + (uint32_t)((wn*32 + p*16 + (q>>1)*8 + r8) * 128);
        #pragma unroll
        for (int ks = 0; ks < 4; ks++) {
            uint32_t colA = ((uint32_t)(ks*32 + (q>>1)*16)) ^ axor;
            uint32_t colB = ((uint32_t)(ks*32 + (q&1)*16)) ^ axor;
            uint32_t af[4][4], bf[4][2];
            #pragma unroll
            for (int mt = 0; mt < 4; mt++)
                ldsm4(af[mt][0], af[mt][1], af[mt][2], af[mt][3],
                      rowA[mt] + colA);
            #pragma unroll
            for (int p = 0; p < 2; p++)
                ldsm4(bf[2*p][0], bf[2*p][1], bf[2*p+1][0], bf[2*p+1][1],
                      rowB[p] + colB);
            #pragma unroll
            for (int mt = 0; mt < 4; mt++)
                #pragma unroll
                for (int nt = 0; nt < 4; nt++)
                    mma_f16(acc[mt][nt], af[mt], bf[nt]);
        }
    }

    /* epilogue */
    int grp = lane >> 2, qid = lane & 3;
    #pragma unroll
    for (int mt = 0; mt < 4; mt++) {
        int r0 = bm + wm*64 + mt*16 + grp;
        #pragma unroll
        for (int nt = 0; nt < 4; nt++) {
            int c0 = bn + wn*32 + nt*8 + qid*2;
            float b0 = bias[c0], b1 = bias[c0+1];
            float v0 = acc[mt][nt][0] + b0;
            float v1 = acc[mt][nt][1] + b1;
            float v2 = acc[mt][nt][2] + b0;
            float v3 = acc[mt][nt][3] + b1;
            if (RELU) {
                v0 = fmaxf(v0, 0.f); v1 = fmaxf(v1, 0.f);
                v2 = fmaxf(v2, 0.f); v3 = fmaxf(v3, 0.f);
            }
            if (OUT16) {
                *(__half2*)&C16[(size_t)r0*N + c0] = __floats2half2_rn(v0, v1);
                *(__half2*)&C16[(size_t)(r0+8)*N + c0] = __floats2half2_rn(v2, v3);
            } else {
                *(float2*)&C32[(size_t)r0*N + c0]     = make_float2(v0, v1);
                *(float2*)&C32[(size_t)(r0+8)*N + c0] = make_float2(v2, v3);
            }
        }
    }
}

__global__ __launch_bounds__(256, 2)
void gemm_f32(const __half* __restrict__ A, const __half* __restrict__ Bt,
              const float* __restrict__ bias, float* __restrict__ C,
              int N, int K) {
    gemm_body<0,0>(A, Bt, bias, C, (__half*)0, N, K,
                   blockIdx.y*128, blockIdx.x*128);
}

__global__ __launch_bounds__(256, 2)
void gemm_h16_relu(const __half* __restrict__ A, const __half* __restrict__ Bt,
                   const float* __restrict__ bias, __half* __restrict__ C,
                   int N, int K) {
    gemm_body<1,1>(A, Bt, bias, (float*)0, C, N, K,
                   blockIdx.y*128, blockIdx.x*128);
}

/* fused q/k/v: blockIdx.z selects weight/bias/output, fp16 out */
__global__ __launch_bounds__(256, 2)
void gemm_qkv(const __half* __restrict__ A, const __half* __restrict__ BtL,
              const float* __restrict__ bq, const float* __restrict__ bk,
              const float* __restrict__ bv,
              __half* __restrict__ Cq, __half* __restrict__ Ck,
              __half* __restrict__ Cv) {
    const __half* Bt; const float* bi; __half* C;
    if (blockIdx.z == 0)      { Bt = BtL;          bi = bq; C = Cq; }
    else if (blockIdx.z == 1) { Bt = BtL + 16384;  bi = bk; C = Ck; }
    else                      { Bt = BtL + 32768;  bi = bv; C = Cv; }
    gemm_body<0,1>(A, Bt, bi, (float*)0, C, DD, DD, blockIdx.y*128, 0);
}

/* ------------------ tensor-core attention -------------------------------
   One block per (b,n): 256 threads = 8 warps, warp w = head w.
   Q,K,V (128x128 fp16) staged in smem with 136-half row pitch (ldmatrix
   conflict-free). Per warp: loop 8 query chunks of 16 rows; S = Q@K^T via
   16 HMMA; full-row softmax in registers (ex2.approx, quad shuffles);
   P fragments remapped C->A; O = P@V via ldmatrix.trans + 16 HMMA.       */
__global__ __launch_bounds__(256)
void attn_tc_kernel(const __half* __restrict__ Q,
                    const __half* __restrict__ K,
                    const __half* __restrict__ V,
                    __half* __restrict__ O) {
    extern __shared__ __half sh[];
    int tid = threadIdx.x, lane = tid & 31, wid = tid >> 5;  /* wid = head */
    int bn = blockIdx.x;
    size_t gbase = (size_t)bn * TT * DD;

    /* stage Q,K,V: 128 rows x 16 chunks(16B) x 3 tensors = 6144 chunks */
    for (int i = tid; i < 128*16*3; i += 256) {
        int tz = i / (128*16);
        int rem = i - tz*2048;
        int r = rem >> 4, c16 = rem & 15;
        const __half* g = (tz == 0 ? Q : tz == 1 ? K : V)
                          + gbase + (size_t)r*DD + c16*8;
        uint32_t sm = s2u(sh) + (uint32_t)(tz*ATT_TB*2 + r*ATT_PAD*2 + c16*16);
        cp16(sm, g);
    }
    cp_commit();
    cp_wait_all();
    __syncthreads();

    uint32_t qb = s2u(sh);
    uint32_t kb = qb + ATT_TB*2;
    uint32_t vb = qb + 2*ATT_TB*2;
    uint32_t hoff = (uint32_t)(wid*32);   /* byte offset of head slice */

    int l8 = lane & 7, q4 = lane >> 3;
    int g8 = lane >> 2, tg = lane & 3;
    /* shared ldmatrix x4 addr pattern: rows (q4&1)*8+l8, col half (q4>>1) */
    uint32_t lrow = (uint32_t)(((q4 & 1)*8 + l8) * (ATT_PAD*2));
    uint32_t lcol = hoff + (uint32_t)((q4 >> 1) * 16);

    for (int qc = 0; qc < 8; qc++) {
        /* ---- Q A-fragment ---- */
        uint32_t a[4];
        ldsm4(a[0], a[1], a[2], a[3],
              qb + (uint32_t)(qc*16*(ATT_PAD*2)) + lrow + lcol);

        /* ---- S = Q @ K^T : 16 n-tiles ---- */
        float Sc[16][4];
        #pragma unroll
        for (int u = 0; u < 8; u++) {
            uint32_t b4[4];
            ldsm4(b4[0], b4[1], b4[2], b4[3],
                  kb + (uint32_t)(u*16*(ATT_PAD*2)) + lrow + lcol);
            float* c0 = Sc[2*u]; float* c1 = Sc[2*u+1];
            #pragma unroll
            for (int i = 0; i < 4; i++) { c0[i] = 0.f; c1[i] = 0.f; }
            uint32_t bb0[2] = { b4[0], b4[2] };
            uint32_t bb1[2] = { b4[1], b4[3] };
            mma_f16(c0, a, bb0);
            mma_f16(c1, a, bb1);
        }

        /* ---- softmax over full rows (g8 and g8+8) ---- */
        float mx0 = -1e30f, mx1 = -1e30f;
        #pragma unroll
        for (int nt = 0; nt < 16; nt++) {
            mx0 = fmaxf(mx0, fmaxf(Sc[nt][0], Sc[nt][1]));
            mx1 = fmaxf(mx1, fmaxf(Sc[nt][2], Sc[nt][3]));
        }
        mx0 = fmaxf(mx0, __shfl_xor_sync(0xffffffffu, mx0, 1));
        mx0 = fmaxf(mx0, __shfl_xor_sync(0xffffffffu, mx0, 2));
        mx1 = fmaxf(mx1, __shfl_xor_sync(0xffffffffu, mx1, 1));
        mx1 = fmaxf(mx1, __shfl_xor_sync(0xffffffffu, mx1, 2));
        float ls0 = 0.f, ls1 = 0.f;
        #pragma unroll
        for (int nt = 0; nt < 16; nt++) {
            float p0 = ex2f((Sc[nt][0] - mx0) * SC2);
            float p1 = ex2f((Sc[nt][1] - mx0) * SC2);
            float p2 = ex2f((Sc[nt][2] - mx1) * SC2);
            float p3 = ex2f((Sc[nt][3] - mx1) * SC2);
            Sc[nt][0] = p0; Sc[nt][1] = p1; Sc[nt][2] = p2; Sc[nt][3] = p3;
            ls0 += p0 + p1; ls1 += p2 + p3;
        }
        ls0 += __shfl_xor_sync(0xffffffffu, ls0, 1);
        ls0 += __shfl_xor_sync(0xffffffffu, ls0, 2);
        ls1 += __shfl_xor_sync(0xffffffffu, ls1, 1);
        ls1 += __shfl_xor_sync(0xffffffffu, ls1, 2);
        float inv0 = __fdividef(1.f, ls0);
        float inv1 = __fdividef(1.f, ls1);

        /* ---- O = P @ V : 8 k-chunks, 2 n-tiles ---- */
        float Oc[2][4];
        #pragma unroll
        for (int i = 0; i < 4; i++) { Oc[0][i] = 0.f; Oc[1][i] = 0.f; }
        #pragma unroll
        for (int kc = 0; kc < 8; kc++) {
            uint32_t pa[4];
            pa[0] = h2u(__floats2half2_rn(Sc[2*kc][0],   Sc[2*kc][1]));
            pa[1] = h2u(__floats2half2_rn(Sc[2*kc][2],   Sc[2*kc][3]));
            pa[2] = h2u(__floats2half2_rn(Sc[2*kc+1][0], Sc[2*kc+1][1]));
            pa[3] = h2u(__floats2half2_rn(Sc[2*kc+1][2], Sc[2*kc+1][3]));
            uint32_t v4[4];
            ldsm4t(v4[0], v4[1], v4[2], v4[3],
                   vb + (uint32_t)(kc*16*(ATT_PAD*2)) + lrow + lcol);
            uint32_t vb0[2] = { v4[0], v4[1] };
            uint32_t vb1[2] = { v4[2], v4[3] };
            mma_f16(Oc[0], pa, vb0);
            mma_f16(Oc[1], pa, vb1);
        }

        /* ---- write O (fp16) ---- */
        int row0 = qc*16 + g8;
        #pragma unroll
        for (int nt = 0; nt < 2; nt++) {
            int col = wid*16 + nt*8 + tg*2;
            *(__half2*)&O[gbase + (size_t)row0*DD + col] =
                __floats2half2_rn(Oc[nt][0]*inv0, Oc[nt][1]*inv0);
            *(__half2*)&O[gbase + (size_t)(row0+8)*DD + col] =
                __floats2half2_rn(Oc[nt][2]*inv1, Oc[nt][3]*inv1);
        }
    }
}

/* ------------------ out = LayerNorm(A + Bv) * g + beta (fp32 + fp16) --- */
__global__ void add_ln_kernel(const float* __restrict__ A,
                              const float* __restrict__ Bv,
                              const float* __restrict__ g,
                              const float* __restrict__ bet,
                              float* __restrict__ out,
                              __half* __restrict__ out16) {
    int r = blockIdx.x;
    int tid = threadIdx.x;  /* 128 */
    float x = A[(size_t)r*DD + tid] + Bv[(size_t)r*DD + tid];
    float s = x, sq = x*x;
    #pragma unroll
    for (int o = 16; o > 0; o >>= 1) {
        s  += __shfl_xor_sync(0xffffffffu, s, o);
        sq += __shfl_xor_sync(0xffffffffu, sq, o);
    }
    __shared__ float ss[4], ssq[4];
    int w = tid >> 5, ln = tid & 31;
    if (ln == 0) { ss[w] = s; ssq[w] = sq; }
    __syncthreads();
    s  = ss[0]+ss[1]+ss[2]+ss[3];
    sq = ssq[0]+ssq[1]+ssq[2]+ssq[3];
    float m = s * (1.f/DD);
    float var = sq * (1.f/DD) - m*m;
    float o = (x - m)*rsqrtf(var + EPSV)*g[tid] + bet[tid];
    out[(size_t)r*DD + tid] = o;
    out16[(size_t)r*DD + tid] = __float2half(o);
}

/* ------------------ s[b, t*NA+n] = dot(out_e row, x row) --------------- */
__global__ void dot_kernel() {
    int r  = blockIdx.x*8 + (threadIdx.x >> 5);
    int ln = threadIdx.x & 31;
    const float* a = g_oute + (size_t)r*DD;
    const float* c = g_x    + (size_t)r*DD;
    float s = 0.f;
    #pragma unroll
    for (int j = ln; j < DD; j += 32) s += a[j]*c[j];
    #pragma unroll
    for (int o = 16; o > 0; o >>= 1) s += __shfl_xor_sync(0xffffffffu, s, o);
    if (ln == 0) {
        int b = r / (NA*TT);
        int rem = r % (NA*TT);
        int n = rem >> 7;
        int t = rem & 127;
        g_s[b*NNODE + t*NA + n] = s;
    }
}

__global__ void zero_kernel() {
    int i = blockIdx.x*256 + threadIdx.x;
    if (i < BSZ*NNODE) g_gr[i] = 0.f;
}

/* ------------------ edge segment-sum via atomics ----------------------- */
__global__ void agg_kernel(const int* __restrict__ ei,
                           const float* __restrict__ ew) {
    int i = blockIdx.x*256 + threadIdx.x;
    if (i >= BSZ*EE) return;
    int b = i >> 16;
    int e = i & (EE-1);
    int src = ei[(size_t)b*2*EE + e];
    int dst = ei[(size_t)b*2*EE + EE + e];
    atomicAdd(&g_gr[b*NNODE + dst], ew[(size_t)b*EE + e] * g_s[b*NNODE + src]);
}

/* ------------------ global mean / rsqrt(var) --------------------------- */
__global__ void stats_kernel() {
    int tid = threadIdx.x;  /* 1024 */
    float s = 0.f, sq = 0.f;
    for (int i = tid; i < BSZ*NNODE; i += 1024) {
        float v = g_gr[i];
        s += v; sq += v*v;
    }
    #pragma unroll
    for (int o = 16; o > 0; o >>= 1) {
        s  += __shfl_xor_sync(0xffffffffu, s, o);
        sq += __shfl_xor_sync(0xffffffffu, sq, o);
    }
    __shared__ float ss[32], ssq[32];
    int w = tid >> 5, ln = tid & 31;
    if (ln == 0) { ss[w] = s; ssq[w] = sq; }
    __syncthreads();
    if (tid == 0) {
        float ts = 0.f, tq = 0.f;
        #pragma unroll
        for (int j = 0; j < 32; j++) { ts += ss[j]; tq += ssq[j]; }
        float m = ts / (float)(BSZ*NNODE);
        float var = tq / (float)(BSZ*NNODE) - m*m;
        g_stats[0] = m;
        g_stats[1] = rsqrtf(var + EPSV);
    }
}

/* ------------------ final: out[b,n,t,d] = bn(g)[b,t,n]*lw[d]+lb[d] ----- */
__global__ void final_kernel(const float* __restrict__ bng,
                             const float* __restrict__ bnb,
                             const float* __restrict__ lw,
                             const float* __restrict__ lb,
                             float* __restrict__ out) {
    int i = blockIdx.x*256 + threadIdx.x;
    if (i >= ROWS*DD) return;
    int d = i & 127;
    int r = i >> 7;
    int t = r & 127;
    int bn = r >> 7;
    int n = bn & 63;
    int b = bn >> 6;
    float gv = (g_gr[b*NNODE + t*NA + n] - g_stats[0]) * g_stats[1] * bng[0] + bnb[0];
    out[i] = gv * lw[d] + lb[d];
}

/* ---------------------------------------------------------------------- */
extern "C" void kernel_launch(void* const* d_in, const int* in_sizes, int n_in,
                              void* d_out, int out_size) {
    const float* ahf  = (const float*)d_in[0];
    const int*   ei   = (const int*)  d_in[1];
    const float* ew   = (const float*)d_in[2];
    const float* hw   = (const float*)d_in[3];
    const float* hb   = (const float*)d_in[4];
    const float* wq   = (const float*)d_in[5];
    const float* bq   = (const float*)d_in[6];
    const float* wk   = (const float*)d_in[7];
    const float* bk   = (const float*)d_in[8];
    const float* wv   = (const float*)d_in[9];
    const float* bv   = (const float*)d_in[10];
    const float* wo   = (const float*)d_in[11];
    const float* bo   = (const float*)d_in[12];
    const float* ln1g = (const float*)d_in[13];
    const float* ln1b = (const float*)d_in[14];
    const float* fw1  = (const float*)d_in[15];
    const float* fb1  = (const float*)d_in[16];
    const float* fw2  = (const float*)d_in[17];
    const float* fb2  = (const float*)d_in[18];
    const float* ln2g = (const float*)d_in[19];
    const float* ln2b = (const float*)d_in[20];
    const float* bng  = (const float*)d_in[21];
    const float* bnb  = (const float*)d_in[22];
    const float* lgw  = (const float*)d_in[23];
    const float* lgb  = (const float*)d_in[24];
    float* out = (float*)d_out;

    float *poute, *ph1, *ptmp;
    __half *pwt, *poute16, *pq16, *pk16, *pv16, *pao16, *ph116, *pff116;
    cudaGetSymbolAddress((void**)&poute,   g_oute);
    cudaGetSymbolAddress((void**)&ph1,     g_h1);
    cudaGetSymbolAddress((void**)&ptmp,    g_tmp);
    cudaGetSymbolAddress((void**)&pwt,     g_wt);
    cudaGetSymbolAddress((void**)&poute16, g_oute16);
    cudaGetSymbolAddress((void**)&pq16,    g_q16);
    cudaGetSymbolAddress((void**)&pk16,    g_k16);
    cudaGetSymbolAddress((void**)&pv16,    g_v16);
    cudaGetSymbolAddress((void**)&pao16,   g_ao16);
    cudaGetSymbolAddress((void**)&ph116,   g_h116);
    cudaGetSymbolAddress((void**)&pff116,  g_ff116);

    static int smem_set = 0;
    if (!smem_set) {
        cudaFuncSetAttribute(attn_tc_kernel,
            cudaFuncAttributeMaxDynamicSharedMemorySize, ATT_SMEM);
        smem_set = 1;
    }

    tp_kernel<<<(3*WT_LAYER + 255)/256, 256>>>(wq, wk, wv, wo, fw1, fw2);
    embed_kernel<<<(ROWS*DD)/256, 256>>>(ahf, hw, hb);

    dim3 gqkv(1, ROWS/128, 3);    /* (1, 256, 3) */
    dim3 gp(1, ROWS/128);         /* (1, 256) */
    dim3 g1(DFF/128, ROWS/128);   /* (4, 256) */

    for (int l = 0; l < LL; l++) {
        const __half* WtL = pwt + (size_t)l*WT_LAYER;
        gemm_qkv<<<gqkv, 256>>>(poute16, WtL,
                                bq + l*DD, bk + l*DD, bv + l*DD,
                                pq16, pk16, pv16);
        attn_tc_kernel<<<BSZ*NA, 256, ATT_SMEM>>>(pq16, pk16, pv16, pao16);
        gemm_f32<<<gp, 256>>>(pao16, WtL + 49152, bo + l*DD, ptmp, DD, DD);
        add_ln_kernel<<<ROWS, 128>>>(poute, ptmp, ln1g + l*DD, ln1b + l*DD,
                                     ph1, ph116);
        gemm_h16_relu<<<g1, 256>>>(ph116, WtL + WT_W1, fb1 + l*DFF,
                                   pff116, DFF, DD);
        gemm_f32<<<gp, 256>>>(pff116, WtL + WT_W2, fb2 + l*DD, ptmp, DD, DFF);
        add_ln_kernel<<<ROWS, 128>>>(ph1, ptmp, ln2g + l*DD, ln2b + l*DD,
                                     poute, poute16);
    }

    dot_kernel<<<ROWS/8, 256>>>();
    zero_kernel<<<(BSZ*NNODE + 255)/256, 256>>>();
    agg_kernel<<<(BSZ*EE + 255)/256, 256>>>(ei, ew);
    stats_kernel<<<1, 1024>>>();
    final_kernel<<<(ROWS*DD)/256, 256>>>(bng, bnb, lgw, lgb, out);
}